// round 16
// baseline (speedup 1.0000x reference)
#include <cuda_runtime.h>
#include <cuda_bf16.h>
#include <math.h>
#include <stdint.h>

#define NN 50000
#define NE 800000
#define NT 17

__device__ float    g_nf0[NN * 64];
__device__ float    g_nf1[NN * 64];
__device__ float    g_ef0[NE * 64];
__device__ float    g_ef1[NE * 64];
__device__ float    g_hsrc[NN * 128];
__device__ float    g_htgt[NN * 128];
__device__ float    g_aggr[NN * 64];
__device__ unsigned g_segmax[NN * NT];
__device__ float    g_segsum[NN * NT];
__device__ float    g_ex[NE];
__device__ float    g_sig[NE];
__device__ int      g_seg[NE];
__device__ float    g_emb[NN * 64];
__device__ int      g_ntype[NN];

__device__ __forceinline__ unsigned fkey(float f) {
    unsigned u = __float_as_uint(f);
    return (u & 0x80000000u) ? ~u : (u | 0x80000000u);
}
__device__ __forceinline__ float funkey(unsigned u) {
    return __uint_as_float((u & 0x80000000u) ? (u & 0x7fffffffu) : ~u);
}
__device__ __forceinline__ uint32_t f2tf(float x) {
    uint32_t r;
    asm("cvt.rna.tf32.f32 %0, %1;" : "=r"(r) : "f"(x));
    return r;
}
__device__ __forceinline__ void tsplit(float x, uint32_t& h, uint32_t& l) {
    h = f2tf(x);
    l = f2tf(x - __uint_as_float(h));
}
__device__ __forceinline__ void mma_tf32(float* c, const uint32_t* a, uint32_t b0, uint32_t b1) {
    asm volatile("mma.sync.aligned.m16n8k8.row.col.f32.tf32.tf32.f32 "
        "{%0,%1,%2,%3}, {%4,%5,%6,%7}, {%8,%9}, {%0,%1,%2,%3};"
        : "+f"(c[0]), "+f"(c[1]), "+f"(c[2]), "+f"(c[3])
        : "r"(a[0]), "r"(a[1]), "r"(a[2]), "r"(a[3]), "r"(b0), "r"(b1));
}
__device__ __forceinline__ void redg2(float* p, float x, float y) {
    asm volatile("red.global.add.v2.f32 [%0], {%1, %2};" :: "l"(p), "f"(x), "f"(y) : "memory");
}

// ---- A-fragment stores ----
__device__ __forceinline__ void stA_kb(char* hi, char* lo, int row, int k0, float4 v, int kb) {
    int reg = ((row >> 3) & 1) | (((k0 >> 2) & 1) << 1);
    uint32_t base = ((((row >> 4) * kb + (k0 >> 3)) << 5) + ((row & 7) << 2)) * 16 + reg * 4;
    uint32_t h, l;
    tsplit(v.x, h, l); *(uint32_t*)(hi + base) = h;      *(uint32_t*)(lo + base) = l;
    tsplit(v.y, h, l); *(uint32_t*)(hi + base + 16) = h; *(uint32_t*)(lo + base + 16) = l;
    tsplit(v.z, h, l); *(uint32_t*)(hi + base + 32) = h; *(uint32_t*)(lo + base + 32) = l;
    tsplit(v.w, h, l); *(uint32_t*)(hi + base + 48) = h; *(uint32_t*)(lo + base + 48) = l;
}
// fp32 single-plane A-fragment store
__device__ __forceinline__ void stA32f(char* ab, int row, int k0, float4 v, int kb) {
    int reg = ((row >> 3) & 1) | (((k0 >> 2) & 1) << 1);
    char* p = ab + (size_t)(((((row >> 4) * kb + (k0 >> 3)) << 5) + ((row & 7) << 2)) * 16 + reg * 4);
    *(float*)(p)      = v.x;
    *(float*)(p + 16) = v.y;
    *(float*)(p + 32) = v.z;
    *(float*)(p + 48) = v.w;
}
// ---- W-fragment store (packed {hi0,hi1,lo0,lo1}) ----
__device__ __forceinline__ void stW_kb(char* wf, int k, int n, float v, int kb) {
    int ln = ((n & 7) << 2) | (k & 3), reg = (k >> 2) & 1;
    size_t fo = (size_t)(((((n >> 3) * kb) + (k >> 3)) << 5) + ln) * 16;
    uint32_t h, l; tsplit(v, h, l);
    *(uint32_t*)(wf + fo + reg * 4) = h;
    *(uint32_t*)(wf + fo + 8 + reg * 4) = l;
}

// ==================== edge-message kernel (R12, proven; steps 0-1) ====================
#define E_A0  0u
#define E_A1  32768u
#define E_W1  65536u
#define E_W2  131072u
#define E_SB  196608u
#define EMS   197376u
// head-fused variant extras
#define EH2_W  197376u
#define EH2_SB 230144u
#define EMSH   230912u

__global__ void __launch_bounds__(256, 1)
edge_msg_tf32(const float* __restrict__ ef, const int* __restrict__ src,
              const int* __restrict__ tgt,
              const float* __restrict__ hsrc, const float* __restrict__ htgt,
              const float* __restrict__ W1, const float* __restrict__ B1,
              const float* __restrict__ W2, const float* __restrict__ B2,
              float* __restrict__ m_out, float* __restrict__ aggr)
{
    extern __shared__ char sm[];
    float* sb = (float*)(sm + E_SB);
    int t = threadIdx.x, lane = t & 31, rb = t >> 5;

    for (int idx = t; idx < 64 * 128; idx += 256) {
        int k = idx >> 7, n = idx & 127;
        stW_kb(sm + E_W1, k, n, W1[(128 + k) * 128 + n], 8);
    }
    for (int idx = t; idx < 128 * 64; idx += 256) {
        int k = idx >> 6, n = idx & 63;
        stW_kb(sm + E_W2, k, n, W2[k * 64 + n], 16);
    }
    if (t < 128) sb[t] = B1[t];
    if (t < 64)  sb[128 + t] = B2[t];

    int r0 = rb * 16 + (lane >> 2);
    int c0 = (lane & 3) * 2;

    int tile0 = blockIdx.x;
    if (tile0 < NE / 128) {
        int e0 = tile0 << 7;
        for (int i = t; i < 2048; i += 256) {
            int row = i >> 4, f4 = i & 15, e = e0 + row;
            stA32f(sm + E_A0, row, f4 * 4, ((const float4*)(ef + (size_t)e * 64))[f4], 8);
        }
    }
    __syncthreads();

    int cur = 0;
    for (int tile = blockIdx.x; tile < NE / 128; tile += gridDim.x) {
        int e0 = tile << 7;
        char* Acur = sm + (cur ? E_A1 : E_A0);
        char* Anxt = sm + (cur ? E_A0 : E_A1);

        int tileN = tile + gridDim.x;
        bool haveN = (tileN < NE / 128);
        float4 pf[8];
        if (haveN) {
            int eN = tileN << 7;
#pragma unroll
            for (int j = 0; j < 8; j++) {
                int i = t + j * 256;
                int row = i >> 4, f4 = i & 15;
                pf[j] = ((const float4*)(ef + (size_t)(eN + row) * 64))[f4];
            }
        }

        int ea = e0 + r0, eb = ea + 8;
        int sa = src[ea], ta = tgt[ea];
        int sbi = src[eb], tb = tgt[eb];
        const float* ha1 = hsrc + (size_t)sa * 128;
        const float* ha2 = htgt + (size_t)ta * 128;
        const float* hb1 = hsrc + (size_t)sbi * 128;
        const float* hb2 = htgt + (size_t)tb * 128;

        float acc[16][4];
#pragma unroll
        for (int nt = 0; nt < 16; nt++)
#pragma unroll
            for (int j = 0; j < 4; j++) acc[nt][j] = 0.f;
#pragma unroll
        for (int ks = 0; ks < 8; ks++) {
            uint4 raw = *(const uint4*)(Acur + ((((rb * 8 + ks) << 5) + lane) << 4));
            uint32_t ah[4], al[4];
            tsplit(__uint_as_float(raw.x), ah[0], al[0]);
            tsplit(__uint_as_float(raw.y), ah[1], al[1]);
            tsplit(__uint_as_float(raw.z), ah[2], al[2]);
            tsplit(__uint_as_float(raw.w), ah[3], al[3]);
#pragma unroll
            for (int nt = 0; nt < 16; nt++) {
                uint4 w = *(const uint4*)(sm + E_W1 + ((((nt * 8 + ks) << 5) + lane) << 4));
                mma_tf32(acc[nt], ah, w.x, w.y);
                mma_tf32(acc[nt], ah, w.z, w.w);
                mma_tf32(acc[nt], al, w.x, w.y);
            }
        }
        if (haveN) {
#pragma unroll
            for (int j = 0; j < 8; j++) {
                int i = t + j * 256;
                int row = i >> 4, f4 = i & 15;
                stA32f(Anxt, row, f4 * 4, pf[j], 8);
            }
        }
#pragma unroll
        for (int nt = 0; nt < 16; nt++) {
            int c = nt * 8 + c0;
            float b0 = sb[c], b1v = sb[c + 1];
            float2 p1 = *(const float2*)(ha1 + c);
            float2 p2 = *(const float2*)(ha2 + c);
            float2 q1 = *(const float2*)(hb1 + c);
            float2 q2 = *(const float2*)(hb2 + c);
            acc[nt][0] = fmaxf(acc[nt][0] + b0 + p1.x + p2.x, 0.f);
            acc[nt][1] = fmaxf(acc[nt][1] + b1v + p1.y + p2.y, 0.f);
            acc[nt][2] = fmaxf(acc[nt][2] + b0 + q1.x + q2.x, 0.f);
            acc[nt][3] = fmaxf(acc[nt][3] + b1v + q1.y + q2.y, 0.f);
        }
        float acc2[8][4];
#pragma unroll
        for (int nt = 0; nt < 8; nt++)
#pragma unroll
            for (int j = 0; j < 4; j++) acc2[nt][j] = 0.f;
#pragma unroll
        for (int b = 0; b < 16; b++) {
            float a4[4];
#pragma unroll
            for (int h = 0; h < 2; h++) {
                int srcl = (lane & 28) | ((lane & 3) >> 1) | (h << 1);
#pragma unroll
                for (int r = 0; r < 2; r++) {
                    float v0 = __shfl_sync(0xffffffffu, acc[b][2 * r],     srcl);
                    float v1 = __shfl_sync(0xffffffffu, acc[b][2 * r + 1], srcl);
                    a4[r + 2 * h] = (lane & 1) ? v1 : v0;
                }
            }
            uint32_t ah[4], al[4];
#pragma unroll
            for (int j = 0; j < 4; j++) tsplit(a4[j], ah[j], al[j]);
#pragma unroll
            for (int nt = 0; nt < 8; nt++) {
                uint4 w = *(const uint4*)(sm + E_W2 + ((((nt * 16 + b) << 5) + lane) << 4));
                mma_tf32(acc2[nt], ah, w.x, w.y);
                mma_tf32(acc2[nt], ah, w.z, w.w);
                mma_tf32(acc2[nt], al, w.x, w.y);
            }
        }
        {
            size_t tao = (size_t)ta * 64, tbo = (size_t)tb * 64;
#pragma unroll
            for (int nt = 0; nt < 8; nt++) {
                int c = nt * 8 + c0;
                float b0 = sb[128 + c], b1v = sb[128 + c + 1];
                float v00 = acc2[nt][0] + b0, v01 = acc2[nt][1] + b1v;
                float v10 = acc2[nt][2] + b0, v11 = acc2[nt][3] + b1v;
                *(float2*)(m_out + (size_t)ea * 64 + c) = make_float2(v00, v01);
                *(float2*)(m_out + (size_t)eb * 64 + c) = make_float2(v10, v11);
                redg2(aggr + tao + c, v00, v01);
                redg2(aggr + tbo + c, v10, v11);
            }
        }
        __syncthreads();
        cur ^= 1;
    }
}

// ==================== edge-message + fused edge-pred head (step 3 only) ====================
__global__ void __launch_bounds__(256, 1)
edge_msg_head(const float* __restrict__ ef, const int* __restrict__ src,
              const int* __restrict__ tgt,
              const float* __restrict__ hsrc, const float* __restrict__ htgt,
              const float* __restrict__ W1, const float* __restrict__ B1,
              const float* __restrict__ W2, const float* __restrict__ B2,
              const float* __restrict__ hW1, const float* __restrict__ hB1,
              const float* __restrict__ hW2v, const float* __restrict__ hB2,
              float* __restrict__ m_out, float* __restrict__ aggr,
              float* __restrict__ sig_out)
{
    extern __shared__ char sm[];
    float* sb  = (float*)(sm + E_SB);
    float* hsb = (float*)(sm + EH2_SB);
    int t = threadIdx.x, lane = t & 31, rb = t >> 5;

    for (int idx = t; idx < 64 * 128; idx += 256) {
        int k = idx >> 7, n = idx & 127;
        stW_kb(sm + E_W1, k, n, W1[(128 + k) * 128 + n], 8);
    }
    for (int idx = t; idx < 128 * 64; idx += 256) {
        int k = idx >> 6, n = idx & 63;
        stW_kb(sm + E_W2, k, n, W2[k * 64 + n], 16);
    }
    for (int idx = t; idx < 64 * 64; idx += 256) {
        int k = idx >> 6, n = idx & 63;
        stW_kb(sm + EH2_W, k, n, hW1[idx], 8);
    }
    if (t < 128) sb[t] = B1[t];
    if (t < 64)  sb[128 + t] = B2[t];
    if (t < 64)  { hsb[t] = hB1[t]; hsb[64 + t] = hW2v[t]; }
    if (t == 0)  hsb[128] = hB2[0];

    int r0 = rb * 16 + (lane >> 2);
    int c0 = (lane & 3) * 2;

    int tile0 = blockIdx.x;
    if (tile0 < NE / 128) {
        int e0 = tile0 << 7;
        for (int i = t; i < 2048; i += 256) {
            int row = i >> 4, f4 = i & 15, e = e0 + row;
            stA32f(sm + E_A0, row, f4 * 4, ((const float4*)(ef + (size_t)e * 64))[f4], 8);
        }
    }
    __syncthreads();

    int cur = 0;
    for (int tile = blockIdx.x; tile < NE / 128; tile += gridDim.x) {
        int e0 = tile << 7;
        char* Acur = sm + (cur ? E_A1 : E_A0);
        char* Anxt = sm + (cur ? E_A0 : E_A1);

        int tileN = tile + gridDim.x;
        bool haveN = (tileN < NE / 128);
        float4 pf[8];
        if (haveN) {
            int eN = tileN << 7;
#pragma unroll
            for (int j = 0; j < 8; j++) {
                int i = t + j * 256;
                int row = i >> 4, f4 = i & 15;
                pf[j] = ((const float4*)(ef + (size_t)(eN + row) * 64))[f4];
            }
        }

        int ea = e0 + r0, eb = ea + 8;
        int sa = src[ea], ta = tgt[ea];
        int sbi = src[eb], tb = tgt[eb];
        const float* ha1 = hsrc + (size_t)sa * 128;
        const float* ha2 = htgt + (size_t)ta * 128;
        const float* hb1 = hsrc + (size_t)sbi * 128;
        const float* hb2 = htgt + (size_t)tb * 128;

        float acc[16][4];
#pragma unroll
        for (int nt = 0; nt < 16; nt++)
#pragma unroll
            for (int j = 0; j < 4; j++) acc[nt][j] = 0.f;
#pragma unroll
        for (int ks = 0; ks < 8; ks++) {
            uint4 raw = *(const uint4*)(Acur + ((((rb * 8 + ks) << 5) + lane) << 4));
            uint32_t ah[4], al[4];
            tsplit(__uint_as_float(raw.x), ah[0], al[0]);
            tsplit(__uint_as_float(raw.y), ah[1], al[1]);
            tsplit(__uint_as_float(raw.z), ah[2], al[2]);
            tsplit(__uint_as_float(raw.w), ah[3], al[3]);
#pragma unroll
            for (int nt = 0; nt < 16; nt++) {
                uint4 w = *(const uint4*)(sm + E_W1 + ((((nt * 8 + ks) << 5) + lane) << 4));
                mma_tf32(acc[nt], ah, w.x, w.y);
                mma_tf32(acc[nt], ah, w.z, w.w);
                mma_tf32(acc[nt], al, w.x, w.y);
            }
        }
        if (haveN) {
#pragma unroll
            for (int j = 0; j < 8; j++) {
                int i = t + j * 256;
                int row = i >> 4, f4 = i & 15;
                stA32f(Anxt, row, f4 * 4, pf[j], 8);
            }
        }
#pragma unroll
        for (int nt = 0; nt < 16; nt++) {
            int c = nt * 8 + c0;
            float b0 = sb[c], b1v = sb[c + 1];
            float2 p1 = *(const float2*)(ha1 + c);
            float2 p2 = *(const float2*)(ha2 + c);
            float2 q1 = *(const float2*)(hb1 + c);
            float2 q2 = *(const float2*)(hb2 + c);
            acc[nt][0] = fmaxf(acc[nt][0] + b0 + p1.x + p2.x, 0.f);
            acc[nt][1] = fmaxf(acc[nt][1] + b1v + p1.y + p2.y, 0.f);
            acc[nt][2] = fmaxf(acc[nt][2] + b0 + q1.x + q2.x, 0.f);
            acc[nt][3] = fmaxf(acc[nt][3] + b1v + q1.y + q2.y, 0.f);
        }
        float acc2[8][4];
#pragma unroll
        for (int nt = 0; nt < 8; nt++)
#pragma unroll
            for (int j = 0; j < 4; j++) acc2[nt][j] = 0.f;
#pragma unroll
        for (int b = 0; b < 16; b++) {
            float a4[4];
#pragma unroll
            for (int h = 0; h < 2; h++) {
                int srcl = (lane & 28) | ((lane & 3) >> 1) | (h << 1);
#pragma unroll
                for (int r = 0; r < 2; r++) {
                    float v0 = __shfl_sync(0xffffffffu, acc[b][2 * r],     srcl);
                    float v1 = __shfl_sync(0xffffffffu, acc[b][2 * r + 1], srcl);
                    a4[r + 2 * h] = (lane & 1) ? v1 : v0;
                }
            }
            uint32_t ah[4], al[4];
#pragma unroll
            for (int j = 0; j < 4; j++) tsplit(a4[j], ah[j], al[j]);
#pragma unroll
            for (int nt = 0; nt < 8; nt++) {
                uint4 w = *(const uint4*)(sm + E_W2 + ((((nt * 16 + b) << 5) + lane) << 4));
                mma_tf32(acc2[nt], ah, w.x, w.y);
                mma_tf32(acc2[nt], ah, w.z, w.w);
                mma_tf32(acc2[nt], al, w.x, w.y);
            }
        }
        // epilogue2: bias into acc2, write m + aggr
        {
            size_t tao = (size_t)ta * 64, tbo = (size_t)tb * 64;
#pragma unroll
            for (int nt = 0; nt < 8; nt++) {
                int c = nt * 8 + c0;
                float b0 = sb[128 + c], b1v = sb[128 + c + 1];
                acc2[nt][0] += b0;  acc2[nt][1] += b1v;
                acc2[nt][2] += b0;  acc2[nt][3] += b1v;
                *(float2*)(m_out + (size_t)ea * 64 + c) = make_float2(acc2[nt][0], acc2[nt][1]);
                *(float2*)(m_out + (size_t)eb * 64 + c) = make_float2(acc2[nt][2], acc2[nt][3]);
                redg2(aggr + tao + c, acc2[nt][0], acc2[nt][1]);
                redg2(aggr + tbo + c, acc2[nt][2], acc2[nt][3]);
            }
        }
        // ---- fused edge-pred head: h = relu(m @ ec_w1 + b1); pred = h . ec_w2 ----
        {
            float acch[8][4];
#pragma unroll
            for (int nt = 0; nt < 8; nt++)
#pragma unroll
                for (int j = 0; j < 4; j++) acch[nt][j] = 0.f;
#pragma unroll
            for (int b = 0; b < 8; b++) {
                float a4[4];
#pragma unroll
                for (int h = 0; h < 2; h++) {
                    int srcl = (lane & 28) | ((lane & 3) >> 1) | (h << 1);
#pragma unroll
                    for (int r = 0; r < 2; r++) {
                        float v0 = __shfl_sync(0xffffffffu, acc2[b][2 * r],     srcl);
                        float v1 = __shfl_sync(0xffffffffu, acc2[b][2 * r + 1], srcl);
                        a4[r + 2 * h] = (lane & 1) ? v1 : v0;
                    }
                }
                uint32_t ah[4], al[4];
#pragma unroll
                for (int j = 0; j < 4; j++) tsplit(a4[j], ah[j], al[j]);
#pragma unroll
                for (int nt = 0; nt < 8; nt++) {
                    uint4 w = *(const uint4*)(sm + EH2_W + ((((nt * 8 + b) << 5) + lane) << 4));
                    mma_tf32(acch[nt], ah, w.x, w.y);
                    mma_tf32(acch[nt], ah, w.z, w.w);
                    mma_tf32(acch[nt], al, w.x, w.y);
                }
            }
            float pA = 0.f, pB = 0.f;
#pragma unroll
            for (int nt = 0; nt < 8; nt++) {
                int c = nt * 8 + c0;
                float b0 = hsb[c], b1v = hsb[c + 1];
                float w0 = hsb[64 + c], w1 = hsb[64 + c + 1];
                pA += fmaxf(acch[nt][0] + b0, 0.f) * w0 + fmaxf(acch[nt][1] + b1v, 0.f) * w1;
                pB += fmaxf(acch[nt][2] + b0, 0.f) * w0 + fmaxf(acch[nt][3] + b1v, 0.f) * w1;
            }
            pA += __shfl_xor_sync(0xffffffffu, pA, 1);
            pA += __shfl_xor_sync(0xffffffffu, pA, 2);
            pB += __shfl_xor_sync(0xffffffffu, pB, 1);
            pB += __shfl_xor_sync(0xffffffffu, pB, 2);
            if ((lane & 3) == 0) {
                sig_out[ea] = 1.f / (1.f + expf(-(pA + hsb[128])));
                sig_out[eb] = 1.f / (1.f + expf(-(pB + hsb[128])));
            }
        }
        __syncthreads();
        cur ^= 1;
    }
}

// ==================== encoder MLP (R15, 2 CTAs/SM) ====================
#define M_A   0u
#define M_W1  32768u
#define M_W2  65536u
#define M_SB  98304u
#define EMS2  98816u

__global__ void __launch_bounds__(256, 2)
mlp2_mma(const float* __restrict__ X, float* __restrict__ Y,
         const float* __restrict__ W1, const float* __restrict__ B1,
         const float* __restrict__ W2, const float* __restrict__ B2, int M)
{
    extern __shared__ char sm[];
    float* sb = (float*)(sm + M_SB);
    int t = threadIdx.x, lane = t & 31, rb = t >> 5;

    for (int idx = t; idx < 4096; idx += 256) {
        int k = idx >> 6, n = idx & 63;
        stW_kb(sm + M_W1, k, n, W1[idx], 8);
        stW_kb(sm + M_W2, k, n, W2[idx], 8);
    }
    if (t < 64) { sb[t] = B1[t]; sb[64 + t] = B2[t]; }
    __syncthreads();

    int r0 = rb * 16 + (lane >> 2);
    int c0 = (lane & 3) * 2;
    int ntiles = (M + 127) >> 7;

    for (int tile = blockIdx.x; tile < ntiles; tile += gridDim.x) {
        int row0 = tile << 7;
        for (int i = t; i < 2048; i += 256) {
            int row = i >> 4, f4 = i & 15, e = row0 + row;
            float4 v = (e < M) ? ((const float4*)(X + (size_t)e * 64))[f4]
                               : make_float4(0.f, 0.f, 0.f, 0.f);
            stA32f(sm + M_A, row, f4 * 4, v, 8);
        }
        __syncthreads();

        float acc[8][4];
#pragma unroll
        for (int nt = 0; nt < 8; nt++)
#pragma unroll
            for (int j = 0; j < 4; j++) acc[nt][j] = 0.f;
#pragma unroll
        for (int ks = 0; ks < 8; ks++) {
            uint4 raw = *(const uint4*)(sm + M_A + ((((rb * 8 + ks) << 5) + lane) << 4));
            uint32_t ah[4], al[4];
            tsplit(__uint_as_float(raw.x), ah[0], al[0]);
            tsplit(__uint_as_float(raw.y), ah[1], al[1]);
            tsplit(__uint_as_float(raw.z), ah[2], al[2]);
            tsplit(__uint_as_float(raw.w), ah[3], al[3]);
#pragma unroll
            for (int nt = 0; nt < 8; nt++) {
                uint4 w = *(const uint4*)(sm + M_W1 + ((((nt * 8 + ks) << 5) + lane) << 4));
                mma_tf32(acc[nt], ah, w.x, w.y);
                mma_tf32(acc[nt], ah, w.z, w.w);
                mma_tf32(acc[nt], al, w.x, w.y);
            }
        }
#pragma unroll
        for (int nt = 0; nt < 8; nt++) {
            int c = nt * 8 + c0;
            float b0 = sb[c], b1v = sb[c + 1];
            acc[nt][0] = fmaxf(acc[nt][0] + b0, 0.f);
            acc[nt][1] = fmaxf(acc[nt][1] + b1v, 0.f);
            acc[nt][2] = fmaxf(acc[nt][2] + b0, 0.f);
            acc[nt][3] = fmaxf(acc[nt][3] + b1v, 0.f);
        }
        float acc2[8][4];
#pragma unroll
        for (int nt = 0; nt < 8; nt++)
#pragma unroll
            for (int j = 0; j < 4; j++) acc2[nt][j] = 0.f;
#pragma unroll
        for (int b = 0; b < 8; b++) {
            float a4[4];
#pragma unroll
            for (int h = 0; h < 2; h++) {
                int srcl = (lane & 28) | ((lane & 3) >> 1) | (h << 1);
#pragma unroll
                for (int r = 0; r < 2; r++) {
                    float v0 = __shfl_sync(0xffffffffu, acc[b][2 * r],     srcl);
                    float v1 = __shfl_sync(0xffffffffu, acc[b][2 * r + 1], srcl);
                    a4[r + 2 * h] = (lane & 1) ? v1 : v0;
                }
            }
            uint32_t ah[4], al[4];
#pragma unroll
            for (int j = 0; j < 4; j++) tsplit(a4[j], ah[j], al[j]);
#pragma unroll
            for (int nt = 0; nt < 8; nt++) {
                uint4 w = *(const uint4*)(sm + M_W2 + ((((nt * 8 + b) << 5) + lane) << 4));
                mma_tf32(acc2[nt], ah, w.x, w.y);
                mma_tf32(acc2[nt], ah, w.z, w.w);
                mma_tf32(acc2[nt], al, w.x, w.y);
            }
        }
        {
            int ea = row0 + r0, eb = ea + 8;
#pragma unroll
            for (int nt = 0; nt < 8; nt++) {
                int c = nt * 8 + c0;
                float b0 = sb[64 + c], b1v = sb[64 + c + 1];
                if (ea < M)
                    *(float2*)(Y + (size_t)ea * 64 + c) =
                        make_float2(acc2[nt][0] + b0, acc2[nt][1] + b1v);
                if (eb < M)
                    *(float2*)(Y + (size_t)eb * 64 + c) =
                        make_float2(acc2[nt][2] + b0, acc2[nt][3] + b1v);
            }
        }
        __syncthreads();
    }
}

// ==================== node partials (R13, proven) ====================
#define NP_A0 0u
#define NP_A1 32768u
#define NP_WS 65536u
#define NP_WT 131072u
#define NP_SMEM 196608u

__global__ void __launch_bounds__(256, 1)
npart_mma(const float* __restrict__ nf, const float* __restrict__ W1,
          float* __restrict__ hsrc, float* __restrict__ htgt, int M)
{
    extern __shared__ char sm[];
    int t = threadIdx.x, lane = t & 31, rb = t >> 5;
    for (int idx = t; idx < 64 * 128; idx += 256) {
        int k = idx >> 7, n = idx & 127;
        stW_kb(sm + NP_WS, k, n, W1[k * 128 + n], 8);
        stW_kb(sm + NP_WT, k, n, W1[(64 + k) * 128 + n], 8);
    }
    int r0 = rb * 16 + (lane >> 2), c0 = (lane & 3) * 2;
    int ntiles = (M + 127) >> 7;

    int tile0 = blockIdx.x;
    if (tile0 < ntiles) {
        int row0 = tile0 << 7;
        for (int i = t; i < 2048; i += 256) {
            int row = i >> 4, f4 = i & 15, e = row0 + row;
            float4 v = (e < M) ? ((const float4*)(nf + (size_t)e * 64))[f4]
                               : make_float4(0.f, 0.f, 0.f, 0.f);
            stA32f(sm + NP_A0, row, f4 * 4, v, 8);
        }
    }
    __syncthreads();

    int cur = 0;
    for (int tile = blockIdx.x; tile < ntiles; tile += gridDim.x) {
        int row0 = tile << 7;
        char* Acur = sm + (cur ? NP_A1 : NP_A0);
        char* Anxt = sm + (cur ? NP_A0 : NP_A1);

        int tileN = tile + gridDim.x;
        bool haveN = (tileN < ntiles);
        float4 pf[8];
        if (haveN) {
            int rN = tileN << 7;
#pragma unroll
            for (int j = 0; j < 8; j++) {
                int i = t + j * 256;
                int row = i >> 4, f4 = i & 15, e = rN + row;
                pf[j] = (e < M) ? ((const float4*)(nf + (size_t)e * 64))[f4]
                                : make_float4(0.f, 0.f, 0.f, 0.f);
            }
        }

        int ra = row0 + r0, rbx = ra + 8;
#pragma unroll
        for (int pass = 0; pass < 2; pass++) {
            const char* wf = sm + (pass ? NP_WT : NP_WS);
            float* outp = pass ? htgt : hsrc;
            float acc[16][4];
#pragma unroll
            for (int nt = 0; nt < 16; nt++)
#pragma unroll
                for (int j = 0; j < 4; j++) acc[nt][j] = 0.f;
#pragma unroll
            for (int ks = 0; ks < 8; ks++) {
                uint4 raw = *(const uint4*)(Acur + ((((rb * 8 + ks) << 5) + lane) << 4));
                uint32_t ah[4], al[4];
                tsplit(__uint_as_float(raw.x), ah[0], al[0]);
                tsplit(__uint_as_float(raw.y), ah[1], al[1]);
                tsplit(__uint_as_float(raw.z), ah[2], al[2]);
                tsplit(__uint_as_float(raw.w), ah[3], al[3]);
#pragma unroll
                for (int nt = 0; nt < 16; nt++) {
                    uint4 w = *(const uint4*)(wf + ((((nt * 8 + ks) << 5) + lane) << 4));
                    mma_tf32(acc[nt], ah, w.x, w.y);
                    mma_tf32(acc[nt], ah, w.z, w.w);
                    mma_tf32(acc[nt], al, w.x, w.y);
                }
            }
            if (pass == 0 && haveN) {
#pragma unroll
                for (int j = 0; j < 8; j++) {
                    int i = t + j * 256;
                    int row = i >> 4, f4 = i & 15;
                    stA32f(Anxt, row, f4 * 4, pf[j], 8);
                }
            }
#pragma unroll
            for (int nt = 0; nt < 16; nt++) {
                int c = nt * 8 + c0;
                if (ra < M)
                    *(float2*)(outp + (size_t)ra * 128 + c) = make_float2(acc[nt][0], acc[nt][1]);
                if (rbx < M)
                    *(float2*)(outp + (size_t)rbx * 128 + c) = make_float2(acc[nt][2], acc[nt][3]);
            }
        }
        __syncthreads();
        cur ^= 1;
    }
}

// ==================== node update (R12, unchanged) ====================
#define NU_AHI 0u
#define NU_ALO 65536u
#define NU_WF  131072u
#define NU_SB  196608u
#define NU_SMEM 196864u

__global__ void __launch_bounds__(256, 1)
nupd_mma(const float* __restrict__ nf, const float* __restrict__ aggr,
         const float* __restrict__ W, const float* __restrict__ B,
         float* __restrict__ out, int M)
{
    extern __shared__ char sm[];
    float* sb = (float*)(sm + NU_SB);
    int t = threadIdx.x, lane = t & 31, rb = t >> 5;
    for (int idx = t; idx < 128 * 64; idx += 256) {
        int k = idx >> 6, n = idx & 63;
        stW_kb(sm + NU_WF, k, n, W[k * 64 + n], 16);
    }
    if (t < 64) sb[t] = B[t];
    __syncthreads();
    int r0 = rb * 16 + (lane >> 2), c0 = (lane & 3) * 2;
    int ntiles = (M + 127) >> 7;
    for (int tile = blockIdx.x; tile < ntiles; tile += gridDim.x) {
        int row0 = tile << 7;
        for (int i = t; i < 4096; i += 256) {
            int row = i >> 5, f4 = i & 31, e = row0 + row;
            float4 v = make_float4(0.f, 0.f, 0.f, 0.f);
            if (e < M)
                v = (f4 < 16) ? ((const float4*)(nf + (size_t)e * 64))[f4]
                              : ((const float4*)(aggr + (size_t)e * 64))[f4 - 16];
            stA_kb(sm + NU_AHI, sm + NU_ALO, row, f4 * 4, v, 16);
        }
        __syncthreads();
        float acc[8][4];
#pragma unroll
        for (int nt = 0; nt < 8; nt++)
#pragma unroll
            for (int j = 0; j < 4; j++) acc[nt][j] = 0.f;
#pragma unroll
        for (int ks = 0; ks < 16; ks++) {
            uint32_t ao = ((((rb * 16 + ks) << 5) + lane) << 4);
            uint32_t ah[4], al[4];
            *(uint4*)ah = *(const uint4*)(sm + NU_AHI + ao);
            *(uint4*)al = *(const uint4*)(sm + NU_ALO + ao);
#pragma unroll
            for (int nt = 0; nt < 8; nt++) {
                uint4 w = *(const uint4*)(sm + NU_WF + ((((nt * 16 + ks) << 5) + lane) << 4));
                mma_tf32(acc[nt], ah, w.x, w.y);
                mma_tf32(acc[nt], ah, w.z, w.w);
                mma_tf32(acc[nt], al, w.x, w.y);
            }
        }
        {
            int ra = row0 + r0, rbx = ra + 8;
#pragma unroll
            for (int nt = 0; nt < 8; nt++) {
                int c = nt * 8 + c0;
                float b0 = sb[c], b1v = sb[c + 1];
                if (ra < M)
                    *(float2*)(out + (size_t)ra * 64 + c) =
                        make_float2(acc[nt][0] + b0, acc[nt][1] + b1v);
                if (rbx < M)
                    *(float2*)(out + (size_t)rbx * 64 + c) =
                        make_float2(acc[nt][2] + b0, acc[nt][3] + b1v);
            }
        }
        __syncthreads();
    }
}

// ==================== node heads (R14, pipelined) ====================
#define NH_A0   0u
#define NH_A1   32768u
#define NH_WF   65536u
#define NH_W2   (65536u + 98304u)
#define NH_SB   (65536u + 98304u + 12288u)
#define NH_SMEM (NH_SB + 2048u)

__global__ void __launch_bounds__(256, 1)
node_heads_mma(const float* __restrict__ nf,
               const float* __restrict__ nc_w1, const float* __restrict__ nc_b1,
               const float* __restrict__ nc_w2, const float* __restrict__ nc_b2,
               const float* __restrict__ cl_w1, const float* __restrict__ cl_b1,
               const float* __restrict__ cl_w2, const float* __restrict__ cl_b2,
               const float* __restrict__ ce_w, const float* __restrict__ ce_b,
               float* __restrict__ node_pred, float* __restrict__ class_pred,
               int* __restrict__ ntype, float* __restrict__ emb, int M)
{
    extern __shared__ char sm[];
    float* sb = (float*)(sm + NH_SB);
    int t = threadIdx.x, lane = t & 31, rb = t >> 5;

    for (int idx = t; idx < 4096; idx += 256) {
        int k = idx >> 6, n = idx & 63;
        stW_kb(sm + NH_WF, k, n,       nc_w1[idx], 8);
        stW_kb(sm + NH_WF, k, n + 64,  cl_w1[idx], 8);
        stW_kb(sm + NH_WF, k, n + 128, ce_w[idx],  8);
    }
    for (int idx = t; idx < 64 * 24; idx += 256) {
        int k = idx / 24, n = idx % 24;
        stW_kb(sm + NH_W2, k, n, (n < 17) ? cl_w2[k * 17 + n] : 0.f, 8);
    }
    if (t < 64) {
        sb[t] = nc_b1[t];
        sb[64 + t] = cl_b1[t];
        sb[128 + t] = ce_b[t];
        sb[192 + t] = nc_w2[t];
    }
    if (t < 24) sb[256 + t] = (t < 17) ? cl_b2[t] : -1e30f;
    if (t == 0) sb[280] = nc_b2[0];

    int r0 = rb * 16 + (lane >> 2), c0 = (lane & 3) * 2;
    int ntiles = (M + 127) >> 7;

    int tile0 = blockIdx.x;
    if (tile0 < ntiles) {
        int row0 = tile0 << 7;
        for (int i = t; i < 2048; i += 256) {
            int row = i >> 4, f4 = i & 15, e = row0 + row;
            float4 v = (e < M) ? ((const float4*)(nf + (size_t)e * 64))[f4]
                               : make_float4(0.f, 0.f, 0.f, 0.f);
            stA32f(sm + NH_A0, row, f4 * 4, v, 8);
        }
    }
    __syncthreads();

    int cur = 0;
    for (int tile = blockIdx.x; tile < ntiles; tile += gridDim.x) {
        int row0 = tile << 7;
        char* Acur = sm + (cur ? NH_A1 : NH_A0);
        char* Anxt = sm + (cur ? NH_A0 : NH_A1);

        int tileN = tile + gridDim.x;
        bool haveN = (tileN < ntiles);
        float4 pf[8];
        if (haveN) {
            int rN = tileN << 7;
#pragma unroll
            for (int j = 0; j < 8; j++) {
                int i = t + j * 256;
                int row = i >> 4, f4 = i & 15, e = rN + row;
                pf[j] = (e < M) ? ((const float4*)(nf + (size_t)e * 64))[f4]
                                : make_float4(0.f, 0.f, 0.f, 0.f);
            }
        }

        float acc[24][4];
#pragma unroll
        for (int nt = 0; nt < 24; nt++)
#pragma unroll
            for (int j = 0; j < 4; j++) acc[nt][j] = 0.f;
#pragma unroll
        for (int ks = 0; ks < 8; ks++) {
            uint4 raw = *(const uint4*)(Acur + ((((rb * 8 + ks) << 5) + lane) << 4));
            uint32_t ah[4], al[4];
            tsplit(__uint_as_float(raw.x), ah[0], al[0]);
            tsplit(__uint_as_float(raw.y), ah[1], al[1]);
            tsplit(__uint_as_float(raw.z), ah[2], al[2]);
            tsplit(__uint_as_float(raw.w), ah[3], al[3]);
#pragma unroll
            for (int nt = 0; nt < 24; nt++) {
                uint4 w = *(const uint4*)(sm + NH_WF + ((((nt * 8 + ks) << 5) + lane) << 4));
                mma_tf32(acc[nt], ah, w.x, w.y);
                mma_tf32(acc[nt], ah, w.z, w.w);
                mma_tf32(acc[nt], al, w.x, w.y);
            }
        }
        if (haveN) {
#pragma unroll
            for (int j = 0; j < 8; j++) {
                int i = t + j * 256;
                int row = i >> 4, f4 = i & 15;
                stA32f(Anxt, row, f4 * 4, pf[j], 8);
            }
        }
        int rA = row0 + r0, rB = rA + 8;
#pragma unroll
        for (int j = 0; j < 8; j++) {
            int c = j * 8 + c0;
            float b0 = sb[128 + c], b1v = sb[128 + c + 1];
            if (rA < M)
                *(float2*)(emb + (size_t)rA * 64 + c) =
                    make_float2(acc[16 + j][0] + b0, acc[16 + j][1] + b1v);
            if (rB < M)
                *(float2*)(emb + (size_t)rB * 64 + c) =
                    make_float2(acc[16 + j][2] + b0, acc[16 + j][3] + b1v);
        }
        float pA = 0.f, pB = 0.f;
#pragma unroll
        for (int j = 0; j < 8; j++) {
            int c = j * 8 + c0;
            float b0 = sb[c], b1v = sb[c + 1];
            float w0 = sb[192 + c], w1 = sb[192 + c + 1];
            pA += fmaxf(acc[j][0] + b0, 0.f) * w0 + fmaxf(acc[j][1] + b1v, 0.f) * w1;
            pB += fmaxf(acc[j][2] + b0, 0.f) * w0 + fmaxf(acc[j][3] + b1v, 0.f) * w1;
        }
        pA += __shfl_xor_sync(0xffffffffu, pA, 1);
        pA += __shfl_xor_sync(0xffffffffu, pA, 2);
        pB += __shfl_xor_sync(0xffffffffu, pB, 1);
        pB += __shfl_xor_sync(0xffffffffu, pB, 2);
        if ((lane & 3) == 0) {
            if (rA < M) node_pred[rA] = pA + sb[280];
            if (rB < M) node_pred[rB] = pB + sb[280];
        }
#pragma unroll
        for (int j = 0; j < 8; j++) {
            int c = j * 8 + c0;
            float b0 = sb[64 + c], b1v = sb[64 + c + 1];
            acc[8 + j][0] = fmaxf(acc[8 + j][0] + b0, 0.f);
            acc[8 + j][1] = fmaxf(acc[8 + j][1] + b1v, 0.f);
            acc[8 + j][2] = fmaxf(acc[8 + j][2] + b0, 0.f);
            acc[8 + j][3] = fmaxf(acc[8 + j][3] + b1v, 0.f);
        }
        float acc2[3][4];
#pragma unroll
        for (int nt = 0; nt < 3; nt++)
#pragma unroll
            for (int j = 0; j < 4; j++) acc2[nt][j] = 0.f;
#pragma unroll
        for (int b = 0; b < 8; b++) {
            float a4[4];
#pragma unroll
            for (int h = 0; h < 2; h++) {
                int srcl = (lane & 28) | ((lane & 3) >> 1) | (h << 1);
#pragma unroll
                for (int r = 0; r < 2; r++) {
                    float v0 = __shfl_sync(0xffffffffu, acc[8 + b][2 * r],     srcl);
                    float v1 = __shfl_sync(0xffffffffu, acc[8 + b][2 * r + 1], srcl);
                    a4[r + 2 * h] = (lane & 1) ? v1 : v0;
                }
            }
            uint32_t ah[4], al[4];
#pragma unroll
            for (int j = 0; j < 4; j++) tsplit(a4[j], ah[j], al[j]);
#pragma unroll
            for (int nt = 0; nt < 3; nt++) {
                uint4 w = *(const uint4*)(sm + NH_W2 + ((((nt * 8 + b) << 5) + lane) << 4));
                mma_tf32(acc2[nt], ah, w.x, w.y);
                mma_tf32(acc2[nt], ah, w.z, w.w);
                mma_tf32(acc2[nt], al, w.x, w.y);
            }
        }
        {
            float bvA = -1e30f, bvB = -1e30f;
            int biA = 0, biB = 0;
#pragma unroll
            for (int nt = 0; nt < 3; nt++) {
                int c = nt * 8 + c0;
                float b0 = sb[256 + c], b1v = sb[256 + c + 1];
                float vA0 = acc2[nt][0] + b0, vA1 = acc2[nt][1] + b1v;
                float vB0 = acc2[nt][2] + b0, vB1 = acc2[nt][3] + b1v;
                if (c < 17) {
                    if (rA < M) class_pred[(size_t)rA * 17 + c] = vA0;
                    if (rB < M) class_pred[(size_t)rB * 17 + c] = vB0;
                    if (vA0 > bvA) { bvA = vA0; biA = c; }
                    if (vB0 > bvB) { bvB = vB0; biB = c; }
                }
                if (c + 1 < 17) {
                    if (rA < M) class_pred[(size_t)rA * 17 + c + 1] = vA1;
                    if (rB < M) class_pred[(size_t)rB * 17 + c + 1] = vB1;
                    if (vA1 > bvA) { bvA = vA1; biA = c + 1; }
                    if (vB1 > bvB) { bvB = vB1; biB = c + 1; }
                }
            }
#pragma unroll
            for (int o = 1; o <= 2; o <<= 1) {
                float ovA = __shfl_xor_sync(0xffffffffu, bvA, o);
                int   oiA = __shfl_xor_sync(0xffffffffu, biA, o);
                if (ovA > bvA || (ovA == bvA && oiA < biA)) { bvA = ovA; biA = oiA; }
                float ovB = __shfl_xor_sync(0xffffffffu, bvB, o);
                int   oiB = __shfl_xor_sync(0xffffffffu, biB, o);
                if (ovB > bvB || (ovB == bvB && oiB < biB)) { bvB = ovB; biB = oiB; }
            }
            if ((lane & 3) == 0) {
                if (rA < M) ntype[rA] = biA;
                if (rB < M) ntype[rB] = biB;
            }
        }
        __syncthreads();
        cur ^= 1;
    }
}

// ==================== edge scores (light gather kernel) ====================
__global__ void __launch_bounds__(256)
edge_scores(const int* __restrict__ src, const int* __restrict__ tgt,
            const float* __restrict__ emb, const int* __restrict__ ntype,
            float* __restrict__ score_out, int* __restrict__ seg_out,
            unsigned* __restrict__ segmax)
{
    int gid = blockIdx.x * blockDim.x + threadIdx.x;
    int e = gid >> 2;
    int l = gid & 3;
    if (e >= NE) return;
    int s = src[e], tg = tgt[e];
    const float4* a = (const float4*)(emb + (size_t)s * 64) + l * 4;
    const float4* b = (const float4*)(emb + (size_t)tg * 64) + l * 4;
    float sc = 0.f;
#pragma unroll
    for (int m = 0; m < 4; m++) {
        float4 x = a[m], y = b[m];
        sc += x.x * y.x + x.y * y.y + x.z * y.z + x.w * y.w;
    }
    sc += __shfl_xor_sync(0xffffffffu, sc, 1);
    sc += __shfl_xor_sync(0xffffffffu, sc, 2);
    if (l == 0) {
        score_out[e] = sc;
        int sg = tg * NT + ntype[s];
        seg_out[e] = sg;
        atomicMax(&segmax[sg], fkey(sc));
    }
}

__global__ void softmax_pass2(const int* __restrict__ seg, const unsigned* __restrict__ segmax,
                              float* __restrict__ score_ex, float* __restrict__ segsum)
{
    int e = blockIdx.x * blockDim.x + threadIdx.x;
    if (e >= NE) return;
    int s = seg[e];
    float ex = expf(score_ex[e] - funkey(segmax[s]));
    score_ex[e] = ex;
    atomicAdd(&segsum[s], ex);
}

__global__ void softmax_pass3(const int* __restrict__ seg, const float* __restrict__ segsum,
                              const float* __restrict__ ex, const float* __restrict__ sig,
                              float* __restrict__ out_edge)
{
    int e = blockIdx.x * blockDim.x + threadIdx.x;
    if (e >= NE) return;
    out_edge[e] = ex[e] / segsum[seg[e]] * sig[e];
}

extern "C" void kernel_launch(void* const* d_in, const int* in_sizes, int n_in,
                              void* d_out, int out_size)
{
    (void)in_sizes; (void)n_in; (void)out_size;
    const float* x     = (const float*)d_in[0];
    const float* eattr = (const float*)d_in[1];
    const int*   ei    = (const int*)d_in[2];
    const float *ne_w1 = (const float*)d_in[4],  *ne_b1 = (const float*)d_in[5];
    const float *ne_w2 = (const float*)d_in[6],  *ne_b2 = (const float*)d_in[7];
    const float *ee_w1 = (const float*)d_in[8],  *ee_b1 = (const float*)d_in[9];
    const float *ee_w2 = (const float*)d_in[10], *ee_b2 = (const float*)d_in[11];
    const float *me_w1 = (const float*)d_in[12], *me_b1 = (const float*)d_in[13];
    const float *me_w2 = (const float*)d_in[14], *me_b2 = (const float*)d_in[15];
    const float *nu_w1 = (const float*)d_in[16], *nu_b1 = (const float*)d_in[17];
    const float *ec_w1 = (const float*)d_in[18], *ec_b1 = (const float*)d_in[19];
    const float *ec_w2 = (const float*)d_in[20], *ec_b2 = (const float*)d_in[21];
    const float *nc_w1 = (const float*)d_in[22], *nc_b1 = (const float*)d_in[23];
    const float *nc_w2 = (const float*)d_in[24], *nc_b2 = (const float*)d_in[25];
    const float *cl_w1 = (const float*)d_in[26], *cl_b1 = (const float*)d_in[27];
    const float *cl_w2 = (const float*)d_in[28], *cl_b2 = (const float*)d_in[29];
    const float *ce_w  = (const float*)d_in[30], *ce_b  = (const float*)d_in[31];

    const int* src = ei;
    const int* tgt = ei + NE;

    float* out       = (float*)d_out;
    float* out_edge  = out;
    float* out_node  = out_edge + NE;
    float* out_class = out_node + NN;
    float* out_nf    = out_class + NN * NT;
    float* out_ef    = out_nf + NN * 64;

    float *nf0, *nf1, *ef0, *ef1, *hsrc, *htgt, *aggr, *segsum, *ex, *sig, *emb;
    unsigned* segmax; int *seg, *ntype;
    cudaGetSymbolAddress((void**)&nf0,    g_nf0);
    cudaGetSymbolAddress((void**)&nf1,    g_nf1);
    cudaGetSymbolAddress((void**)&ef0,    g_ef0);
    cudaGetSymbolAddress((void**)&ef1,    g_ef1);
    cudaGetSymbolAddress((void**)&hsrc,   g_hsrc);
    cudaGetSymbolAddress((void**)&htgt,   g_htgt);
    cudaGetSymbolAddress((void**)&aggr,   g_aggr);
    cudaGetSymbolAddress((void**)&segmax, g_segmax);
    cudaGetSymbolAddress((void**)&segsum, g_segsum);
    cudaGetSymbolAddress((void**)&ex,     g_ex);
    cudaGetSymbolAddress((void**)&sig,    g_sig);
    cudaGetSymbolAddress((void**)&seg,    g_seg);
    cudaGetSymbolAddress((void**)&emb,    g_emb);
    cudaGetSymbolAddress((void**)&ntype,  g_ntype);

    cudaFuncSetAttribute(edge_msg_tf32, cudaFuncAttributeMaxDynamicSharedMemorySize, EMS);
    cudaFuncSetAttribute(edge_msg_head, cudaFuncAttributeMaxDynamicSharedMemorySize, EMSH);
    cudaFuncSetAttribute(mlp2_mma, cudaFuncAttributeMaxDynamicSharedMemorySize, EMS2);
    cudaFuncSetAttribute(npart_mma, cudaFuncAttributeMaxDynamicSharedMemorySize, NP_SMEM);
    cudaFuncSetAttribute(nupd_mma, cudaFuncAttributeMaxDynamicSharedMemorySize, NU_SMEM);
    cudaFuncSetAttribute(node_heads_mma, cudaFuncAttributeMaxDynamicSharedMemorySize, NH_SMEM);

    mlp2_mma<<<296, 256, EMS2>>>(x,     nf0, ne_w1, ne_b1, ne_w2, ne_b2, NN);
    mlp2_mma<<<296, 256, EMS2>>>(eattr, ef0, ee_w1, ee_b1, ee_w2, ee_b2, NE);

    const float* nf_in = nf0;  float* nf_out = nf1;
    const float* ef_in = ef0;  float* ef_out = ef1;
    for (int s = 0; s < 3; s++) {
        if (s == 2) { nf_out = out_nf; ef_out = out_ef; }
        cudaMemsetAsync(aggr, 0, (size_t)NN * 64 * sizeof(float));
        npart_mma<<<148, 256, NP_SMEM>>>(nf_in, me_w1, hsrc, htgt, NN);
        if (s < 2) {
            edge_msg_tf32<<<148, 256, EMS>>>(ef_in, src, tgt, hsrc, htgt,
                                             me_w1, me_b1, me_w2, me_b2, ef_out, aggr);
        } else {
            edge_msg_head<<<148, 256, EMSH>>>(ef_in, src, tgt, hsrc, htgt,
                                              me_w1, me_b1, me_w2, me_b2,
                                              ec_w1, ec_b1, ec_w2, ec_b2,
                                              ef_out, aggr, sig);
        }
        nupd_mma<<<148, 256, NU_SMEM>>>(nf_in, aggr, nu_w1, nu_b1, nf_out, NN);
        nf_in = nf_out; ef_in = ef_out;
        nf_out = (s == 0) ? nf0 : nf1;
        ef_out = (s == 0) ? ef0 : ef1;
    }

    cudaMemsetAsync(segmax, 0, (size_t)NN * NT * sizeof(unsigned));
    cudaMemsetAsync(segsum, 0, (size_t)NN * NT * sizeof(float));

    node_heads_mma<<<148, 256, NH_SMEM>>>(out_nf, nc_w1, nc_b1, nc_w2, nc_b2,
                                          cl_w1, cl_b1, cl_w2, cl_b2, ce_w, ce_b,
                                          out_node, out_class, ntype, emb, NN);
    edge_scores<<<(NE * 4 + 255) / 256, 256>>>(src, tgt, emb, ntype, ex, seg, segmax);
    softmax_pass2<<<(NE + 255) / 256, 256>>>(seg, segmax, ex, segsum);
    softmax_pass3<<<(NE + 255) / 256, 256>>>(seg, segsum, ex, sig, out_edge);
}

// round 17
// speedup vs baseline: 1.0143x; 1.0143x over previous
#include <cuda_runtime.h>
#include <cuda_bf16.h>
#include <math.h>
#include <stdint.h>

#define NN 50000
#define NE 800000
#define NT 17

__device__ float    g_nf0[NN * 64];
__device__ float    g_nf1[NN * 64];
__device__ float    g_ef0[NE * 64];
__device__ float    g_ef1[NE * 64];
__device__ float    g_hsrc[NN * 128];
__device__ float    g_htgt[NN * 128];
__device__ float    g_aggr[NN * 64];
__device__ unsigned g_segmax[NN * NT];
__device__ float    g_segsum[NN * NT];
__device__ float    g_ex[NE];
__device__ float    g_sig[NE];
__device__ int      g_seg[NE];
__device__ float    g_emb[NN * 64];
__device__ int      g_ntype[NN];

__device__ __forceinline__ unsigned fkey(float f) {
    unsigned u = __float_as_uint(f);
    return (u & 0x80000000u) ? ~u : (u | 0x80000000u);
}
__device__ __forceinline__ float funkey(unsigned u) {
    return __uint_as_float((u & 0x80000000u) ? (u & 0x7fffffffu) : ~u);
}
__device__ __forceinline__ uint32_t f2tf(float x) {
    uint32_t r;
    asm("cvt.rna.tf32.f32 %0, %1;" : "=r"(r) : "f"(x));
    return r;
}
__device__ __forceinline__ void tsplit(float x, uint32_t& h, uint32_t& l) {
    h = f2tf(x);
    l = f2tf(x - __uint_as_float(h));
}
__device__ __forceinline__ void mma_tf32(float* c, const uint32_t* a, uint32_t b0, uint32_t b1) {
    asm volatile("mma.sync.aligned.m16n8k8.row.col.f32.tf32.tf32.f32 "
        "{%0,%1,%2,%3}, {%4,%5,%6,%7}, {%8,%9}, {%0,%1,%2,%3};"
        : "+f"(c[0]), "+f"(c[1]), "+f"(c[2]), "+f"(c[3])
        : "r"(a[0]), "r"(a[1]), "r"(a[2]), "r"(a[3]), "r"(b0), "r"(b1));
}
__device__ __forceinline__ void redg2(float* p, float x, float y) {
    asm volatile("red.global.add.v2.f32 [%0], {%1, %2};" :: "l"(p), "f"(x), "f"(y) : "memory");
}

// ---- A-fragment stores ----
__device__ __forceinline__ void stA_kb(char* hi, char* lo, int row, int k0, float4 v, int kb) {
    int reg = ((row >> 3) & 1) | (((k0 >> 2) & 1) << 1);
    uint32_t base = ((((row >> 4) * kb + (k0 >> 3)) << 5) + ((row & 7) << 2)) * 16 + reg * 4;
    uint32_t h, l;
    tsplit(v.x, h, l); *(uint32_t*)(hi + base) = h;      *(uint32_t*)(lo + base) = l;
    tsplit(v.y, h, l); *(uint32_t*)(hi + base + 16) = h; *(uint32_t*)(lo + base + 16) = l;
    tsplit(v.z, h, l); *(uint32_t*)(hi + base + 32) = h; *(uint32_t*)(lo + base + 32) = l;
    tsplit(v.w, h, l); *(uint32_t*)(hi + base + 48) = h; *(uint32_t*)(lo + base + 48) = l;
}
// fp32 single-plane A-fragment store
__device__ __forceinline__ void stA32f(char* ab, int row, int k0, float4 v, int kb) {
    int reg = ((row >> 3) & 1) | (((k0 >> 2) & 1) << 1);
    char* p = ab + (size_t)(((((row >> 4) * kb + (k0 >> 3)) << 5) + ((row & 7) << 2)) * 16 + reg * 4);
    *(float*)(p)      = v.x;
    *(float*)(p + 16) = v.y;
    *(float*)(p + 32) = v.z;
    *(float*)(p + 48) = v.w;
}
// ---- W-fragment store (packed {hi0,hi1,lo0,lo1}) ----
__device__ __forceinline__ void stW_kb(char* wf, int k, int n, float v, int kb) {
    int ln = ((n & 7) << 2) | (k & 3), reg = (k >> 2) & 1;
    size_t fo = (size_t)(((((n >> 3) * kb) + (k >> 3)) << 5) + ln) * 16;
    uint32_t h, l; tsplit(v, h, l);
    *(uint32_t*)(wf + fo + reg * 4) = h;
    *(uint32_t*)(wf + fo + 8 + reg * 4) = l;
}

// ==================== edge-message kernel (R12, proven) ====================
#define E_A0  0u
#define E_A1  32768u
#define E_W1  65536u
#define E_W2  131072u
#define E_SB  196608u
#define EMS   197376u

__global__ void __launch_bounds__(256, 1)
edge_msg_tf32(const float* __restrict__ ef, const int* __restrict__ src,
              const int* __restrict__ tgt,
              const float* __restrict__ hsrc, const float* __restrict__ htgt,
              const float* __restrict__ W1, const float* __restrict__ B1,
              const float* __restrict__ W2, const float* __restrict__ B2,
              float* __restrict__ m_out, float* __restrict__ aggr)
{
    extern __shared__ char sm[];
    float* sb = (float*)(sm + E_SB);
    int t = threadIdx.x, lane = t & 31, rb = t >> 5;

    for (int idx = t; idx < 64 * 128; idx += 256) {
        int k = idx >> 7, n = idx & 127;
        stW_kb(sm + E_W1, k, n, W1[(128 + k) * 128 + n], 8);
    }
    for (int idx = t; idx < 128 * 64; idx += 256) {
        int k = idx >> 6, n = idx & 63;
        stW_kb(sm + E_W2, k, n, W2[k * 64 + n], 16);
    }
    if (t < 128) sb[t] = B1[t];
    if (t < 64)  sb[128 + t] = B2[t];

    int r0 = rb * 16 + (lane >> 2);
    int c0 = (lane & 3) * 2;

    int tile0 = blockIdx.x;
    if (tile0 < NE / 128) {
        int e0 = tile0 << 7;
        for (int i = t; i < 2048; i += 256) {
            int row = i >> 4, f4 = i & 15, e = e0 + row;
            stA32f(sm + E_A0, row, f4 * 4, ((const float4*)(ef + (size_t)e * 64))[f4], 8);
        }
    }
    __syncthreads();

    int cur = 0;
    for (int tile = blockIdx.x; tile < NE / 128; tile += gridDim.x) {
        int e0 = tile << 7;
        char* Acur = sm + (cur ? E_A1 : E_A0);
        char* Anxt = sm + (cur ? E_A0 : E_A1);

        int tileN = tile + gridDim.x;
        bool haveN = (tileN < NE / 128);
        float4 pf[8];
        if (haveN) {
            int eN = tileN << 7;
#pragma unroll
            for (int j = 0; j < 8; j++) {
                int i = t + j * 256;
                int row = i >> 4, f4 = i & 15;
                pf[j] = ((const float4*)(ef + (size_t)(eN + row) * 64))[f4];
            }
        }

        int ea = e0 + r0, eb = ea + 8;
        int sa = src[ea], ta = tgt[ea];
        int sbi = src[eb], tb = tgt[eb];
        const float* ha1 = hsrc + (size_t)sa * 128;
        const float* ha2 = htgt + (size_t)ta * 128;
        const float* hb1 = hsrc + (size_t)sbi * 128;
        const float* hb2 = htgt + (size_t)tb * 128;

        float acc[16][4];
#pragma unroll
        for (int nt = 0; nt < 16; nt++)
#pragma unroll
            for (int j = 0; j < 4; j++) acc[nt][j] = 0.f;
#pragma unroll
        for (int ks = 0; ks < 8; ks++) {
            uint4 raw = *(const uint4*)(Acur + ((((rb * 8 + ks) << 5) + lane) << 4));
            uint32_t ah[4], al[4];
            tsplit(__uint_as_float(raw.x), ah[0], al[0]);
            tsplit(__uint_as_float(raw.y), ah[1], al[1]);
            tsplit(__uint_as_float(raw.z), ah[2], al[2]);
            tsplit(__uint_as_float(raw.w), ah[3], al[3]);
#pragma unroll
            for (int nt = 0; nt < 16; nt++) {
                uint4 w = *(const uint4*)(sm + E_W1 + ((((nt * 8 + ks) << 5) + lane) << 4));
                mma_tf32(acc[nt], ah, w.x, w.y);
                mma_tf32(acc[nt], ah, w.z, w.w);
                mma_tf32(acc[nt], al, w.x, w.y);
            }
        }
        if (haveN) {
#pragma unroll
            for (int j = 0; j < 8; j++) {
                int i = t + j * 256;
                int row = i >> 4, f4 = i & 15;
                stA32f(Anxt, row, f4 * 4, pf[j], 8);
            }
        }
#pragma unroll
        for (int nt = 0; nt < 16; nt++) {
            int c = nt * 8 + c0;
            float b0 = sb[c], b1v = sb[c + 1];
            float2 p1 = *(const float2*)(ha1 + c);
            float2 p2 = *(const float2*)(ha2 + c);
            float2 q1 = *(const float2*)(hb1 + c);
            float2 q2 = *(const float2*)(hb2 + c);
            acc[nt][0] = fmaxf(acc[nt][0] + b0 + p1.x + p2.x, 0.f);
            acc[nt][1] = fmaxf(acc[nt][1] + b1v + p1.y + p2.y, 0.f);
            acc[nt][2] = fmaxf(acc[nt][2] + b0 + q1.x + q2.x, 0.f);
            acc[nt][3] = fmaxf(acc[nt][3] + b1v + q1.y + q2.y, 0.f);
        }
        float acc2[8][4];
#pragma unroll
        for (int nt = 0; nt < 8; nt++)
#pragma unroll
            for (int j = 0; j < 4; j++) acc2[nt][j] = 0.f;
#pragma unroll
        for (int b = 0; b < 16; b++) {
            float a4[4];
#pragma unroll
            for (int h = 0; h < 2; h++) {
                int srcl = (lane & 28) | ((lane & 3) >> 1) | (h << 1);
#pragma unroll
                for (int r = 0; r < 2; r++) {
                    float v0 = __shfl_sync(0xffffffffu, acc[b][2 * r],     srcl);
                    float v1 = __shfl_sync(0xffffffffu, acc[b][2 * r + 1], srcl);
                    a4[r + 2 * h] = (lane & 1) ? v1 : v0;
                }
            }
            uint32_t ah[4], al[4];
#pragma unroll
            for (int j = 0; j < 4; j++) tsplit(a4[j], ah[j], al[j]);
#pragma unroll
            for (int nt = 0; nt < 8; nt++) {
                uint4 w = *(const uint4*)(sm + E_W2 + ((((nt * 16 + b) << 5) + lane) << 4));
                mma_tf32(acc2[nt], ah, w.x, w.y);
                mma_tf32(acc2[nt], ah, w.z, w.w);
                mma_tf32(acc2[nt], al, w.x, w.y);
            }
        }
        {
            size_t tao = (size_t)ta * 64, tbo = (size_t)tb * 64;
#pragma unroll
            for (int nt = 0; nt < 8; nt++) {
                int c = nt * 8 + c0;
                float b0 = sb[128 + c], b1v = sb[128 + c + 1];
                float v00 = acc2[nt][0] + b0, v01 = acc2[nt][1] + b1v;
                float v10 = acc2[nt][2] + b0, v11 = acc2[nt][3] + b1v;
                *(float2*)(m_out + (size_t)ea * 64 + c) = make_float2(v00, v01);
                *(float2*)(m_out + (size_t)eb * 64 + c) = make_float2(v10, v11);
                redg2(aggr + tao + c, v00, v01);
                redg2(aggr + tbo + c, v10, v11);
            }
        }
        __syncthreads();
        cur ^= 1;
    }
}

// ==================== encoder MLP (R15, 2 CTAs/SM) ====================
#define M_A   0u
#define M_W1  32768u
#define M_W2  65536u
#define M_SB  98304u
#define EMS2  98816u

__global__ void __launch_bounds__(256, 2)
mlp2_mma(const float* __restrict__ X, float* __restrict__ Y,
         const float* __restrict__ W1, const float* __restrict__ B1,
         const float* __restrict__ W2, const float* __restrict__ B2, int M)
{
    extern __shared__ char sm[];
    float* sb = (float*)(sm + M_SB);
    int t = threadIdx.x, lane = t & 31, rb = t >> 5;

    for (int idx = t; idx < 4096; idx += 256) {
        int k = idx >> 6, n = idx & 63;
        stW_kb(sm + M_W1, k, n, W1[idx], 8);
        stW_kb(sm + M_W2, k, n, W2[idx], 8);
    }
    if (t < 64) { sb[t] = B1[t]; sb[64 + t] = B2[t]; }
    __syncthreads();

    int r0 = rb * 16 + (lane >> 2);
    int c0 = (lane & 3) * 2;
    int ntiles = (M + 127) >> 7;

    for (int tile = blockIdx.x; tile < ntiles; tile += gridDim.x) {
        int row0 = tile << 7;
        for (int i = t; i < 2048; i += 256) {
            int row = i >> 4, f4 = i & 15, e = row0 + row;
            float4 v = (e < M) ? ((const float4*)(X + (size_t)e * 64))[f4]
                               : make_float4(0.f, 0.f, 0.f, 0.f);
            stA32f(sm + M_A, row, f4 * 4, v, 8);
        }
        __syncthreads();

        float acc[8][4];
#pragma unroll
        for (int nt = 0; nt < 8; nt++)
#pragma unroll
            for (int j = 0; j < 4; j++) acc[nt][j] = 0.f;
#pragma unroll
        for (int ks = 0; ks < 8; ks++) {
            uint4 raw = *(const uint4*)(sm + M_A + ((((rb * 8 + ks) << 5) + lane) << 4));
            uint32_t ah[4], al[4];
            tsplit(__uint_as_float(raw.x), ah[0], al[0]);
            tsplit(__uint_as_float(raw.y), ah[1], al[1]);
            tsplit(__uint_as_float(raw.z), ah[2], al[2]);
            tsplit(__uint_as_float(raw.w), ah[3], al[3]);
#pragma unroll
            for (int nt = 0; nt < 8; nt++) {
                uint4 w = *(const uint4*)(sm + M_W1 + ((((nt * 8 + ks) << 5) + lane) << 4));
                mma_tf32(acc[nt], ah, w.x, w.y);
                mma_tf32(acc[nt], ah, w.z, w.w);
                mma_tf32(acc[nt], al, w.x, w.y);
            }
        }
#pragma unroll
        for (int nt = 0; nt < 8; nt++) {
            int c = nt * 8 + c0;
            float b0 = sb[c], b1v = sb[c + 1];
            acc[nt][0] = fmaxf(acc[nt][0] + b0, 0.f);
            acc[nt][1] = fmaxf(acc[nt][1] + b1v, 0.f);
            acc[nt][2] = fmaxf(acc[nt][2] + b0, 0.f);
            acc[nt][3] = fmaxf(acc[nt][3] + b1v, 0.f);
        }
        float acc2[8][4];
#pragma unroll
        for (int nt = 0; nt < 8; nt++)
#pragma unroll
            for (int j = 0; j < 4; j++) acc2[nt][j] = 0.f;
#pragma unroll
        for (int b = 0; b < 8; b++) {
            float a4[4];
#pragma unroll
            for (int h = 0; h < 2; h++) {
                int srcl = (lane & 28) | ((lane & 3) >> 1) | (h << 1);
#pragma unroll
                for (int r = 0; r < 2; r++) {
                    float v0 = __shfl_sync(0xffffffffu, acc[b][2 * r],     srcl);
                    float v1 = __shfl_sync(0xffffffffu, acc[b][2 * r + 1], srcl);
                    a4[r + 2 * h] = (lane & 1) ? v1 : v0;
                }
            }
            uint32_t ah[4], al[4];
#pragma unroll
            for (int j = 0; j < 4; j++) tsplit(a4[j], ah[j], al[j]);
#pragma unroll
            for (int nt = 0; nt < 8; nt++) {
                uint4 w = *(const uint4*)(sm + M_W2 + ((((nt * 8 + b) << 5) + lane) << 4));
                mma_tf32(acc2[nt], ah, w.x, w.y);
                mma_tf32(acc2[nt], ah, w.z, w.w);
                mma_tf32(acc2[nt], al, w.x, w.y);
            }
        }
        {
            int ea = row0 + r0, eb = ea + 8;
#pragma unroll
            for (int nt = 0; nt < 8; nt++) {
                int c = nt * 8 + c0;
                float b0 = sb[64 + c], b1v = sb[64 + c + 1];
                if (ea < M)
                    *(float2*)(Y + (size_t)ea * 64 + c) =
                        make_float2(acc2[nt][0] + b0, acc2[nt][1] + b1v);
                if (eb < M)
                    *(float2*)(Y + (size_t)eb * 64 + c) =
                        make_float2(acc2[nt][2] + b0, acc2[nt][3] + b1v);
            }
        }
        __syncthreads();
    }
}

// ==================== node partials (R13 + fused aggr zeroing) ====================
#define NP_A0 0u
#define NP_A1 32768u
#define NP_WS 65536u
#define NP_WT 131072u
#define NP_SMEM 196608u

__global__ void __launch_bounds__(256, 1)
npart_mma(const float* __restrict__ nf, const float* __restrict__ W1,
          float* __restrict__ hsrc, float* __restrict__ htgt,
          float* __restrict__ aggr, int M)
{
    extern __shared__ char sm[];
    int t = threadIdx.x, lane = t & 31, rb = t >> 5;
    for (int idx = t; idx < 64 * 128; idx += 256) {
        int k = idx >> 7, n = idx & 127;
        stW_kb(sm + NP_WS, k, n, W1[k * 128 + n], 8);
        stW_kb(sm + NP_WT, k, n, W1[(64 + k) * 128 + n], 8);
    }
    int r0 = rb * 16 + (lane >> 2), c0 = (lane & 3) * 2;
    int ntiles = (M + 127) >> 7;

    int tile0 = blockIdx.x;
    if (tile0 < ntiles) {
        int row0 = tile0 << 7;
        for (int i = t; i < 2048; i += 256) {
            int row = i >> 4, f4 = i & 15, e = row0 + row;
            float4 v = (e < M) ? ((const float4*)(nf + (size_t)e * 64))[f4]
                               : make_float4(0.f, 0.f, 0.f, 0.f);
            stA32f(sm + NP_A0, row, f4 * 4, v, 8);
        }
    }
    __syncthreads();

    int cur = 0;
    for (int tile = blockIdx.x; tile < ntiles; tile += gridDim.x) {
        int row0 = tile << 7;
        char* Acur = sm + (cur ? NP_A1 : NP_A0);
        char* Anxt = sm + (cur ? NP_A0 : NP_A1);

        // fused: zero this tile's aggr rows (runs before edge_msg on the stream)
        {
            float4 z = make_float4(0.f, 0.f, 0.f, 0.f);
            for (int i = t; i < 2048; i += 256) {
                int row = i >> 4, f4 = i & 15, e = row0 + row;
                if (e < M) ((float4*)(aggr + (size_t)e * 64))[f4] = z;
            }
        }

        int tileN = tile + gridDim.x;
        bool haveN = (tileN < ntiles);
        float4 pf[8];
        if (haveN) {
            int rN = tileN << 7;
#pragma unroll
            for (int j = 0; j < 8; j++) {
                int i = t + j * 256;
                int row = i >> 4, f4 = i & 15, e = rN + row;
                pf[j] = (e < M) ? ((const float4*)(nf + (size_t)e * 64))[f4]
                                : make_float4(0.f, 0.f, 0.f, 0.f);
            }
        }

        int ra = row0 + r0, rbx = ra + 8;
#pragma unroll
        for (int pass = 0; pass < 2; pass++) {
            const char* wf = sm + (pass ? NP_WT : NP_WS);
            float* outp = pass ? htgt : hsrc;
            float acc[16][4];
#pragma unroll
            for (int nt = 0; nt < 16; nt++)
#pragma unroll
                for (int j = 0; j < 4; j++) acc[nt][j] = 0.f;
#pragma unroll
            for (int ks = 0; ks < 8; ks++) {
                uint4 raw = *(const uint4*)(Acur + ((((rb * 8 + ks) << 5) + lane) << 4));
                uint32_t ah[4], al[4];
                tsplit(__uint_as_float(raw.x), ah[0], al[0]);
                tsplit(__uint_as_float(raw.y), ah[1], al[1]);
                tsplit(__uint_as_float(raw.z), ah[2], al[2]);
                tsplit(__uint_as_float(raw.w), ah[3], al[3]);
#pragma unroll
                for (int nt = 0; nt < 16; nt++) {
                    uint4 w = *(const uint4*)(wf + ((((nt * 8 + ks) << 5) + lane) << 4));
                    mma_tf32(acc[nt], ah, w.x, w.y);
                    mma_tf32(acc[nt], ah, w.z, w.w);
                    mma_tf32(acc[nt], al, w.x, w.y);
                }
            }
            if (pass == 0 && haveN) {
#pragma unroll
                for (int j = 0; j < 8; j++) {
                    int i = t + j * 256;
                    int row = i >> 4, f4 = i & 15;
                    stA32f(Anxt, row, f4 * 4, pf[j], 8);
                }
            }
#pragma unroll
            for (int nt = 0; nt < 16; nt++) {
                int c = nt * 8 + c0;
                if (ra < M)
                    *(float2*)(outp + (size_t)ra * 128 + c) = make_float2(acc[nt][0], acc[nt][1]);
                if (rbx < M)
                    *(float2*)(outp + (size_t)rbx * 128 + c) = make_float2(acc[nt][2], acc[nt][3]);
            }
        }
        __syncthreads();
        cur ^= 1;
    }
}

// ==================== node update (R12, unchanged) ====================
#define NU_AHI 0u
#define NU_ALO 65536u
#define NU_WF  131072u
#define NU_SB  196608u
#define NU_SMEM 196864u

__global__ void __launch_bounds__(256, 1)
nupd_mma(const float* __restrict__ nf, const float* __restrict__ aggr,
         const float* __restrict__ W, const float* __restrict__ B,
         float* __restrict__ out, int M)
{
    extern __shared__ char sm[];
    float* sb = (float*)(sm + NU_SB);
    int t = threadIdx.x, lane = t & 31, rb = t >> 5;
    for (int idx = t; idx < 128 * 64; idx += 256) {
        int k = idx >> 6, n = idx & 63;
        stW_kb(sm + NU_WF, k, n, W[k * 64 + n], 16);
    }
    if (t < 64) sb[t] = B[t];
    __syncthreads();
    int r0 = rb * 16 + (lane >> 2), c0 = (lane & 3) * 2;
    int ntiles = (M + 127) >> 7;
    for (int tile = blockIdx.x; tile < ntiles; tile += gridDim.x) {
        int row0 = tile << 7;
        for (int i = t; i < 4096; i += 256) {
            int row = i >> 5, f4 = i & 31, e = row0 + row;
            float4 v = make_float4(0.f, 0.f, 0.f, 0.f);
            if (e < M)
                v = (f4 < 16) ? ((const float4*)(nf + (size_t)e * 64))[f4]
                              : ((const float4*)(aggr + (size_t)e * 64))[f4 - 16];
            stA_kb(sm + NU_AHI, sm + NU_ALO, row, f4 * 4, v, 16);
        }
        __syncthreads();
        float acc[8][4];
#pragma unroll
        for (int nt = 0; nt < 8; nt++)
#pragma unroll
            for (int j = 0; j < 4; j++) acc[nt][j] = 0.f;
#pragma unroll
        for (int ks = 0; ks < 16; ks++) {
            uint32_t ao = ((((rb * 16 + ks) << 5) + lane) << 4);
            uint32_t ah[4], al[4];
            *(uint4*)ah = *(const uint4*)(sm + NU_AHI + ao);
            *(uint4*)al = *(const uint4*)(sm + NU_ALO + ao);
#pragma unroll
            for (int nt = 0; nt < 8; nt++) {
                uint4 w = *(const uint4*)(sm + NU_WF + ((((nt * 16 + ks) << 5) + lane) << 4));
                mma_tf32(acc[nt], ah, w.x, w.y);
                mma_tf32(acc[nt], ah, w.z, w.w);
                mma_tf32(acc[nt], al, w.x, w.y);
            }
        }
        {
            int ra = row0 + r0, rbx = ra + 8;
#pragma unroll
            for (int nt = 0; nt < 8; nt++) {
                int c = nt * 8 + c0;
                float b0 = sb[c], b1v = sb[c + 1];
                if (ra < M)
                    *(float2*)(out + (size_t)ra * 64 + c) =
                        make_float2(acc[nt][0] + b0, acc[nt][1] + b1v);
                if (rbx < M)
                    *(float2*)(out + (size_t)rbx * 64 + c) =
                        make_float2(acc[nt][2] + b0, acc[nt][3] + b1v);
            }
        }
        __syncthreads();
    }
}

// ==================== node heads (R14 + fused segmax/segsum zeroing) ====================
#define NH_A0   0u
#define NH_A1   32768u
#define NH_WF   65536u
#define NH_W2   (65536u + 98304u)
#define NH_SB   (65536u + 98304u + 12288u)
#define NH_SMEM (NH_SB + 2048u)

__global__ void __launch_bounds__(256, 1)
node_heads_mma(const float* __restrict__ nf,
               const float* __restrict__ nc_w1, const float* __restrict__ nc_b1,
               const float* __restrict__ nc_w2, const float* __restrict__ nc_b2,
               const float* __restrict__ cl_w1, const float* __restrict__ cl_b1,
               const float* __restrict__ cl_w2, const float* __restrict__ cl_b2,
               const float* __restrict__ ce_w, const float* __restrict__ ce_b,
               float* __restrict__ node_pred, float* __restrict__ class_pred,
               int* __restrict__ ntype, float* __restrict__ emb,
               unsigned* __restrict__ segmax, float* __restrict__ segsum, int M)
{
    extern __shared__ char sm[];
    float* sb = (float*)(sm + NH_SB);
    int t = threadIdx.x, lane = t & 31, rb = t >> 5;

    for (int idx = t; idx < 4096; idx += 256) {
        int k = idx >> 6, n = idx & 63;
        stW_kb(sm + NH_WF, k, n,       nc_w1[idx], 8);
        stW_kb(sm + NH_WF, k, n + 64,  cl_w1[idx], 8);
        stW_kb(sm + NH_WF, k, n + 128, ce_w[idx],  8);
    }
    for (int idx = t; idx < 64 * 24; idx += 256) {
        int k = idx / 24, n = idx % 24;
        stW_kb(sm + NH_W2, k, n, (n < 17) ? cl_w2[k * 17 + n] : 0.f, 8);
    }
    if (t < 64) {
        sb[t] = nc_b1[t];
        sb[64 + t] = cl_b1[t];
        sb[128 + t] = ce_b[t];
        sb[192 + t] = nc_w2[t];
    }
    if (t < 24) sb[256 + t] = (t < 17) ? cl_b2[t] : -1e30f;
    if (t == 0) sb[280] = nc_b2[0];

    int r0 = rb * 16 + (lane >> 2), c0 = (lane & 3) * 2;
    int ntiles = (M + 127) >> 7;

    int tile0 = blockIdx.x;
    if (tile0 < ntiles) {
        int row0 = tile0 << 7;
        for (int i = t; i < 2048; i += 256) {
            int row = i >> 4, f4 = i & 15, e = row0 + row;
            float4 v = (e < M) ? ((const float4*)(nf + (size_t)e * 64))[f4]
                               : make_float4(0.f, 0.f, 0.f, 0.f);
            stA32f(sm + NH_A0, row, f4 * 4, v, 8);
        }
    }
    __syncthreads();

    int cur = 0;
    for (int tile = blockIdx.x; tile < ntiles; tile += gridDim.x) {
        int row0 = tile << 7;
        char* Acur = sm + (cur ? NH_A1 : NH_A0);
        char* Anxt = sm + (cur ? NH_A0 : NH_A1);

        // fused: zero this tile's segmax/segsum entries (before edge_head/softmax)
        for (int i = t; i < 2176; i += 256) {
            int row = i / 17, c = i % 17;
            int e = row0 + row;
            if (e < M) {
                segmax[(size_t)e * NT + c] = 0u;
                segsum[(size_t)e * NT + c] = 0.f;
            }
        }

        int tileN = tile + gridDim.x;
        bool haveN = (tileN < ntiles);
        float4 pf[8];
        if (haveN) {
            int rN = tileN << 7;
#pragma unroll
            for (int j = 0; j < 8; j++) {
                int i = t + j * 256;
                int row = i >> 4, f4 = i & 15, e = rN + row;
                pf[j] = (e < M) ? ((const float4*)(nf + (size_t)e * 64))[f4]
                                : make_float4(0.f, 0.f, 0.f, 0.f);
            }
        }

        float acc[24][4];
#pragma unroll
        for (int nt = 0; nt < 24; nt++)
#pragma unroll
            for (int j = 0; j < 4; j++) acc[nt][j] = 0.f;
#pragma unroll
        for (int ks = 0; ks < 8; ks++) {
            uint4 raw = *(const uint4*)(Acur + ((((rb * 8 + ks) << 5) + lane) << 4));
            uint32_t ah[4], al[4];
            tsplit(__uint_as_float(raw.x), ah[0], al[0]);
            tsplit(__uint_as_float(raw.y), ah[1], al[1]);
            tsplit(__uint_as_float(raw.z), ah[2], al[2]);
            tsplit(__uint_as_float(raw.w), ah[3], al[3]);
#pragma unroll
            for (int nt = 0; nt < 24; nt++) {
                uint4 w = *(const uint4*)(sm + NH_WF + ((((nt * 8 + ks) << 5) + lane) << 4));
                mma_tf32(acc[nt], ah, w.x, w.y);
                mma_tf32(acc[nt], ah, w.z, w.w);
                mma_tf32(acc[nt], al, w.x, w.y);
            }
        }
        if (haveN) {
#pragma unroll
            for (int j = 0; j < 8; j++) {
                int i = t + j * 256;
                int row = i >> 4, f4 = i & 15;
                stA32f(Anxt, row, f4 * 4, pf[j], 8);
            }
        }
        int rA = row0 + r0, rB = rA + 8;
#pragma unroll
        for (int j = 0; j < 8; j++) {
            int c = j * 8 + c0;
            float b0 = sb[128 + c], b1v = sb[128 + c + 1];
            if (rA < M)
                *(float2*)(emb + (size_t)rA * 64 + c) =
                    make_float2(acc[16 + j][0] + b0, acc[16 + j][1] + b1v);
            if (rB < M)
                *(float2*)(emb + (size_t)rB * 64 + c) =
                    make_float2(acc[16 + j][2] + b0, acc[16 + j][3] + b1v);
        }
        float pA = 0.f, pB = 0.f;
#pragma unroll
        for (int j = 0; j < 8; j++) {
            int c = j * 8 + c0;
            float b0 = sb[c], b1v = sb[c + 1];
            float w0 = sb[192 + c], w1 = sb[192 + c + 1];
            pA += fmaxf(acc[j][0] + b0, 0.f) * w0 + fmaxf(acc[j][1] + b1v, 0.f) * w1;
            pB += fmaxf(acc[j][2] + b0, 0.f) * w0 + fmaxf(acc[j][3] + b1v, 0.f) * w1;
        }
        pA += __shfl_xor_sync(0xffffffffu, pA, 1);
        pA += __shfl_xor_sync(0xffffffffu, pA, 2);
        pB += __shfl_xor_sync(0xffffffffu, pB, 1);
        pB += __shfl_xor_sync(0xffffffffu, pB, 2);
        if ((lane & 3) == 0) {
            if (rA < M) node_pred[rA] = pA + sb[280];
            if (rB < M) node_pred[rB] = pB + sb[280];
        }
#pragma unroll
        for (int j = 0; j < 8; j++) {
            int c = j * 8 + c0;
            float b0 = sb[64 + c], b1v = sb[64 + c + 1];
            acc[8 + j][0] = fmaxf(acc[8 + j][0] + b0, 0.f);
            acc[8 + j][1] = fmaxf(acc[8 + j][1] + b1v, 0.f);
            acc[8 + j][2] = fmaxf(acc[8 + j][2] + b0, 0.f);
            acc[8 + j][3] = fmaxf(acc[8 + j][3] + b1v, 0.f);
        }
        float acc2[3][4];
#pragma unroll
        for (int nt = 0; nt < 3; nt++)
#pragma unroll
            for (int j = 0; j < 4; j++) acc2[nt][j] = 0.f;
#pragma unroll
        for (int b = 0; b < 8; b++) {
            float a4[4];
#pragma unroll
            for (int h = 0; h < 2; h++) {
                int srcl = (lane & 28) | ((lane & 3) >> 1) | (h << 1);
#pragma unroll
                for (int r = 0; r < 2; r++) {
                    float v0 = __shfl_sync(0xffffffffu, acc[8 + b][2 * r],     srcl);
                    float v1 = __shfl_sync(0xffffffffu, acc[8 + b][2 * r + 1], srcl);
                    a4[r + 2 * h] = (lane & 1) ? v1 : v0;
                }
            }
            uint32_t ah[4], al[4];
#pragma unroll
            for (int j = 0; j < 4; j++) tsplit(a4[j], ah[j], al[j]);
#pragma unroll
            for (int nt = 0; nt < 3; nt++) {
                uint4 w = *(const uint4*)(sm + NH_W2 + ((((nt * 8 + b) << 5) + lane) << 4));
                mma_tf32(acc2[nt], ah, w.x, w.y);
                mma_tf32(acc2[nt], ah, w.z, w.w);
                mma_tf32(acc2[nt], al, w.x, w.y);
            }
        }
        {
            float bvA = -1e30f, bvB = -1e30f;
            int biA = 0, biB = 0;
#pragma unroll
            for (int nt = 0; nt < 3; nt++) {
                int c = nt * 8 + c0;
                float b0 = sb[256 + c], b1v = sb[256 + c + 1];
                float vA0 = acc2[nt][0] + b0, vA1 = acc2[nt][1] + b1v;
                float vB0 = acc2[nt][2] + b0, vB1 = acc2[nt][3] + b1v;
                if (c < 17) {
                    if (rA < M) class_pred[(size_t)rA * 17 + c] = vA0;
                    if (rB < M) class_pred[(size_t)rB * 17 + c] = vB0;
                    if (vA0 > bvA) { bvA = vA0; biA = c; }
                    if (vB0 > bvB) { bvB = vB0; biB = c; }
                }
                if (c + 1 < 17) {
                    if (rA < M) class_pred[(size_t)rA * 17 + c + 1] = vA1;
                    if (rB < M) class_pred[(size_t)rB * 17 + c + 1] = vB1;
                    if (vA1 > bvA) { bvA = vA1; biA = c + 1; }
                    if (vB1 > bvB) { bvB = vB1; biB = c + 1; }
                }
            }
#pragma unroll
            for (int o = 1; o <= 2; o <<= 1) {
                float ovA = __shfl_xor_sync(0xffffffffu, bvA, o);
                int   oiA = __shfl_xor_sync(0xffffffffu, biA, o);
                if (ovA > bvA || (ovA == bvA && oiA < biA)) { bvA = ovA; biA = oiA; }
                float ovB = __shfl_xor_sync(0xffffffffu, bvB, o);
                int   oiB = __shfl_xor_sync(0xffffffffu, biB, o);
                if (ovB > bvB || (ovB == bvB && oiB < biB)) { bvB = ovB; biB = oiB; }
            }
            if ((lane & 3) == 0) {
                if (rA < M) ntype[rA] = biA;
                if (rB < M) ntype[rB] = biB;
            }
        }
        __syncthreads();
        cur ^= 1;
    }
}

// ==================== edge head (R14/R15, pipelined, 2 CTAs/SM) ====================
#define EH_A0  0u
#define EH_A1  32768u
#define EH_WF  65536u
#define EH_SB  98304u
#define EH_SMEM 98816u

__global__ void __launch_bounds__(256, 2)
edge_head_mma(const float* __restrict__ ef, const int* __restrict__ src,
              const int* __restrict__ tgt,
              const float* __restrict__ W1, const float* __restrict__ B1,
              const float* __restrict__ W2v, const float* __restrict__ B2,
              const float* __restrict__ emb, const int* __restrict__ ntype,
              float* __restrict__ sig_out, float* __restrict__ score_out,
              int* __restrict__ seg_out, unsigned* __restrict__ segmax)
{
    extern __shared__ char sm[];
    float* sb1 = (float*)(sm + EH_SB);
    float* sw2 = sb1 + 64;
    int t = threadIdx.x, lane = t & 31, rb = t >> 5;
    for (int idx = t; idx < 4096; idx += 256) {
        int k = idx >> 6, n = idx & 63;
        stW_kb(sm + EH_WF, k, n, W1[idx], 8);
    }
    if (t < 64) { sb1[t] = B1[t]; sw2[t] = W2v[t]; }

    float b2v = B2[0];
    int r0 = rb * 16 + (lane >> 2), c0 = (lane & 3) * 2;
    int j0 = (lane & 3) * 4;

    int tile0 = blockIdx.x;
    if (tile0 < NE / 128) {
        int e0 = tile0 << 7;
        for (int i = t; i < 2048; i += 256) {
            int row = i >> 4, f4 = i & 15, e = e0 + row;
            stA32f(sm + EH_A0, row, f4 * 4, ((const float4*)(ef + (size_t)e * 64))[f4], 8);
        }
    }
    __syncthreads();

    int cur = 0;
    for (int tile = blockIdx.x; tile < NE / 128; tile += gridDim.x) {
        int e0 = tile << 7;
        char* Acur = sm + (cur ? EH_A1 : EH_A0);
        char* Anxt = sm + (cur ? EH_A0 : EH_A1);

        int tileN = tile + gridDim.x;
        bool haveN = (tileN < NE / 128);
        float4 pf[8];
        if (haveN) {
            int eN = tileN << 7;
#pragma unroll
            for (int j = 0; j < 8; j++) {
                int i = t + j * 256;
                int row = i >> 4, f4 = i & 15;
                pf[j] = ((const float4*)(ef + (size_t)(eN + row) * 64))[f4];
            }
        }

        float acc[8][4];
#pragma unroll
        for (int nt = 0; nt < 8; nt++)
#pragma unroll
            for (int j = 0; j < 4; j++) acc[nt][j] = 0.f;
#pragma unroll
        for (int ks = 0; ks < 8; ks++) {
            uint4 raw = *(const uint4*)(Acur + ((((rb * 8 + ks) << 5) + lane) << 4));
            uint32_t ah[4], al[4];
            tsplit(__uint_as_float(raw.x), ah[0], al[0]);
            tsplit(__uint_as_float(raw.y), ah[1], al[1]);
            tsplit(__uint_as_float(raw.z), ah[2], al[2]);
            tsplit(__uint_as_float(raw.w), ah[3], al[3]);
#pragma unroll
            for (int nt = 0; nt < 8; nt++) {
                uint4 w = *(const uint4*)(sm + EH_WF + ((((nt * 8 + ks) << 5) + lane) << 4));
                mma_tf32(acc[nt], ah, w.x, w.y);
                mma_tf32(acc[nt], ah, w.z, w.w);
                mma_tf32(acc[nt], al, w.x, w.y);
            }
        }
        if (haveN) {
#pragma unroll
            for (int j = 0; j < 8; j++) {
                int i = t + j * 256;
                int row = i >> 4, f4 = i & 15;
                stA32f(Anxt, row, f4 * 4, pf[j], 8);
            }
        }
        float pA = 0.f, pB = 0.f;
#pragma unroll
        for (int nt = 0; nt < 8; nt++) {
            int c = nt * 8 + c0;
            float w20 = sw2[c], w21 = sw2[c + 1];
            float bb0 = sb1[c], bb1 = sb1[c + 1];
            pA += fmaxf(acc[nt][0] + bb0, 0.f) * w20 + fmaxf(acc[nt][1] + bb1, 0.f) * w21;
            pB += fmaxf(acc[nt][2] + bb0, 0.f) * w20 + fmaxf(acc[nt][3] + bb1, 0.f) * w21;
        }
        int rA = e0 + r0, rB = rA + 8;
        int sA = src[rA], tA = tgt[rA];
        int sB = src[rB], tB = tgt[rB];
        float scA = 0.f, scB = 0.f;
        {
            const float4* a1 = (const float4*)(emb + (size_t)sA * 64) + j0;
            const float4* a2 = (const float4*)(emb + (size_t)tA * 64) + j0;
            const float4* b1 = (const float4*)(emb + (size_t)sB * 64) + j0;
            const float4* b2 = (const float4*)(emb + (size_t)tB * 64) + j0;
#pragma unroll
            for (int m = 0; m < 4; m++) {
                float4 x = a1[m], y = a2[m];
                scA += x.x * y.x + x.y * y.y + x.z * y.z + x.w * y.w;
                float4 u = b1[m], v = b2[m];
                scB += u.x * v.x + u.y * v.y + u.z * v.z + u.w * v.w;
            }
        }
        pA += __shfl_xor_sync(0xffffffffu, pA, 1);
        pA += __shfl_xor_sync(0xffffffffu, pA, 2);
        pB += __shfl_xor_sync(0xffffffffu, pB, 1);
        pB += __shfl_xor_sync(0xffffffffu, pB, 2);
        scA += __shfl_xor_sync(0xffffffffu, scA, 1);
        scA += __shfl_xor_sync(0xffffffffu, scA, 2);
        scB += __shfl_xor_sync(0xffffffffu, scB, 1);
        scB += __shfl_xor_sync(0xffffffffu, scB, 2);
        if ((lane & 3) == 0) {
            sig_out[rA] = 1.f / (1.f + expf(-(pA + b2v)));
            score_out[rA] = scA;
            int sgA = tA * NT + ntype[sA];
            seg_out[rA] = sgA;
            atomicMax(&segmax[sgA], fkey(scA));
            sig_out[rB] = 1.f / (1.f + expf(-(pB + b2v)));
            score_out[rB] = scB;
            int sgB = tB * NT + ntype[sB];
            seg_out[rB] = sgB;
            atomicMax(&segmax[sgB], fkey(scB));
        }
        __syncthreads();
        cur ^= 1;
    }
}

__global__ void softmax_pass2(const int* __restrict__ seg, const unsigned* __restrict__ segmax,
                              float* __restrict__ score_ex, float* __restrict__ segsum)
{
    int e = blockIdx.x * blockDim.x + threadIdx.x;
    if (e >= NE) return;
    int s = seg[e];
    float ex = expf(score_ex[e] - funkey(segmax[s]));
    score_ex[e] = ex;
    atomicAdd(&segsum[s], ex);
}

__global__ void softmax_pass3(const int* __restrict__ seg, const float* __restrict__ segsum,
                              const float* __restrict__ ex, const float* __restrict__ sig,
                              float* __restrict__ out_edge)
{
    int e = blockIdx.x * blockDim.x + threadIdx.x;
    if (e >= NE) return;
    out_edge[e] = ex[e] / segsum[seg[e]] * sig[e];
}

extern "C" void kernel_launch(void* const* d_in, const int* in_sizes, int n_in,
                              void* d_out, int out_size)
{
    (void)in_sizes; (void)n_in; (void)out_size;
    const float* x     = (const float*)d_in[0];
    const float* eattr = (const float*)d_in[1];
    const int*   ei    = (const int*)d_in[2];
    const float *ne_w1 = (const float*)d_in[4],  *ne_b1 = (const float*)d_in[5];
    const float *ne_w2 = (const float*)d_in[6],  *ne_b2 = (const float*)d_in[7];
    const float *ee_w1 = (const float*)d_in[8],  *ee_b1 = (const float*)d_in[9];
    const float *ee_w2 = (const float*)d_in[10], *ee_b2 = (const float*)d_in[11];
    const float *me_w1 = (const float*)d_in[12], *me_b1 = (const float*)d_in[13];
    const float *me_w2 = (const float*)d_in[14], *me_b2 = (const float*)d_in[15];
    const float *nu_w1 = (const float*)d_in[16], *nu_b1 = (const float*)d_in[17];
    const float *ec_w1 = (const float*)d_in[18], *ec_b1 = (const float*)d_in[19];
    const float *ec_w2 = (const float*)d_in[20], *ec_b2 = (const float*)d_in[21];
    const float *nc_w1 = (const float*)d_in[22], *nc_b1 = (const float*)d_in[23];
    const float *nc_w2 = (const float*)d_in[24], *nc_b2 = (const float*)d_in[25];
    const float *cl_w1 = (const float*)d_in[26], *cl_b1 = (const float*)d_in[27];
    const float *cl_w2 = (const float*)d_in[28], *cl_b2 = (const float*)d_in[29];
    const float *ce_w  = (const float*)d_in[30], *ce_b  = (const float*)d_in[31];

    const int* src = ei;
    const int* tgt = ei + NE;

    float* out       = (float*)d_out;
    float* out_edge  = out;
    float* out_node  = out_edge + NE;
    float* out_class = out_node + NN;
    float* out_nf    = out_class + NN * NT;
    float* out_ef    = out_nf + NN * 64;

    float *nf0, *nf1, *ef0, *ef1, *hsrc, *htgt, *aggr, *segsum, *ex, *sig, *emb;
    unsigned* segmax; int *seg, *ntype;
    cudaGetSymbolAddress((void**)&nf0,    g_nf0);
    cudaGetSymbolAddress((void**)&nf1,    g_nf1);
    cudaGetSymbolAddress((void**)&ef0,    g_ef0);
    cudaGetSymbolAddress((void**)&ef1,    g_ef1);
    cudaGetSymbolAddress((void**)&hsrc,   g_hsrc);
    cudaGetSymbolAddress((void**)&htgt,   g_htgt);
    cudaGetSymbolAddress((void**)&aggr,   g_aggr);
    cudaGetSymbolAddress((void**)&segmax, g_segmax);
    cudaGetSymbolAddress((void**)&segsum, g_segsum);
    cudaGetSymbolAddress((void**)&ex,     g_ex);
    cudaGetSymbolAddress((void**)&sig,    g_sig);
    cudaGetSymbolAddress((void**)&seg,    g_seg);
    cudaGetSymbolAddress((void**)&emb,    g_emb);
    cudaGetSymbolAddress((void**)&ntype,  g_ntype);

    cudaFuncSetAttribute(edge_msg_tf32, cudaFuncAttributeMaxDynamicSharedMemorySize, EMS);
    cudaFuncSetAttribute(mlp2_mma, cudaFuncAttributeMaxDynamicSharedMemorySize, EMS2);
    cudaFuncSetAttribute(npart_mma, cudaFuncAttributeMaxDynamicSharedMemorySize, NP_SMEM);
    cudaFuncSetAttribute(nupd_mma, cudaFuncAttributeMaxDynamicSharedMemorySize, NU_SMEM);
    cudaFuncSetAttribute(node_heads_mma, cudaFuncAttributeMaxDynamicSharedMemorySize, NH_SMEM);
    cudaFuncSetAttribute(edge_head_mma, cudaFuncAttributeMaxDynamicSharedMemorySize, EH_SMEM);

    mlp2_mma<<<296, 256, EMS2>>>(x,     nf0, ne_w1, ne_b1, ne_w2, ne_b2, NN);
    mlp2_mma<<<296, 256, EMS2>>>(eattr, ef0, ee_w1, ee_b1, ee_w2, ee_b2, NE);

    const float* nf_in = nf0;  float* nf_out = nf1;
    const float* ef_in = ef0;  float* ef_out = ef1;
    for (int s = 0; s < 3; s++) {
        if (s == 2) { nf_out = out_nf; ef_out = out_ef; }
        npart_mma<<<148, 256, NP_SMEM>>>(nf_in, me_w1, hsrc, htgt, aggr, NN);
        edge_msg_tf32<<<148, 256, EMS>>>(ef_in, src, tgt, hsrc, htgt,
                                         me_w1, me_b1, me_w2, me_b2, ef_out, aggr);
        nupd_mma<<<148, 256, NU_SMEM>>>(nf_in, aggr, nu_w1, nu_b1, nf_out, NN);
        nf_in = nf_out; ef_in = ef_out;
        nf_out = (s == 0) ? nf0 : nf1;
        ef_out = (s == 0) ? ef0 : ef1;
    }

    node_heads_mma<<<148, 256, NH_SMEM>>>(out_nf, nc_w1, nc_b1, nc_w2, nc_b2,
                                          cl_w1, cl_b1, cl_w2, cl_b2, ce_w, ce_b,
                                          out_node, out_class, ntype, emb,
                                          segmax, segsum, NN);
    edge_head_mma<<<296, 256, EH_SMEM>>>(out_ef, src, tgt, ec_w1, ec_b1, ec_w2, ec_b2,
                                         emb, ntype, sig, ex, seg, segmax);
    softmax_pass2<<<(NE + 255) / 256, 256>>>(seg, segmax, ex, segsum);
    softmax_pass3<<<(NE + 255) / 256, 256>>>(seg, segsum, ex, sig, out_edge);
}